// round 1
// baseline (speedup 1.0000x reference)
#include <cuda_runtime.h>
#include <math.h>

#define NN 10000
#define NE 160000
#define MM 9
#define CC 64
#define HH 8

// ---------------- scratch (static device globals; no allocation) ----------------
__device__ float    g_xs[NN*MM*CC];      // node src-linear   (23 MB)
__device__ float    g_xd[NN*MM*CC];      // node dst-linear   (23 MB)
__device__ float    g_wlc[(size_t)NE*192]; // radial weights  (123 MB)
__device__ float    g_logit[NE*HH];
__device__ unsigned g_nmax[NN*HH];       // monotone-mapped float max
__device__ float    g_denom[NN*HH];
__device__ float    g_acc[NN*MM*CC];

// monotone float<->uint mapping for atomicMax on floats (handles negatives)
__device__ __forceinline__ unsigned fkey(float f){
    int i = __float_as_int(f);
    return (i >= 0) ? ((unsigned)i ^ 0x80000000u) : ~(unsigned)i;
}
__device__ __forceinline__ float fdec(unsigned u){
    int i = (u & 0x80000000u) ? (int)(u ^ 0x80000000u) : (int)(~u);
    return __int_as_float(i);
}

__global__ void k_init(){
    int i = blockIdx.x*blockDim.x + threadIdx.x;
    int st = gridDim.x*blockDim.x;
    for (int t = i; t < NN*MM*CC; t += st) g_acc[t] = 0.f;
    for (int t = i; t < NN*HH;    t += st){ g_denom[t] = 0.f; g_nmax[t] = fkey(-INFINITY); }
}

// ---------------- K1: node linear: x_src = x@Wsrc + bsrc(m0), x_dst = x@Wdst ----
__global__ __launch_bounds__(256) void k_node(
    const float* __restrict__ xin, const float* __restrict__ Ws,
    const float* __restrict__ bs,  const float* __restrict__ Wd)
{
    extern __shared__ float sm[];
    float* WsT = sm;                 // 64*68 (transposed, padded)
    float* WdT = WsT + 64*68;
    float* bss = WdT + 64*68;        // 64
    float* ins = bss + 64;           // 4*576
    int tid = threadIdx.x;
    for (int t = tid; t < 4096; t += 256){ int k = t>>6, d = t&63; WsT[d*68+k] = Ws[t]; WdT[d*68+k] = Wd[t]; }
    if (tid < 64) bss[tid] = bs[tid];
    __syncthreads();
    int slot = tid>>6, j = tid&63;
    for (int base = blockIdx.x*4; base < NN; base += gridDim.x*4){
        int n = base + slot; bool v = n < NN;
        __syncthreads();
        if (v){
            #pragma unroll
            for (int m = 0; m < MM; m++) ins[slot*576 + m*64 + j] = xin[(size_t)n*576 + m*64 + j];
        }
        __syncthreads();
        if (v){
            const float4* ws4 = (const float4*)(WsT + j*68);
            const float4* wd4 = (const float4*)(WdT + j*68);
            for (int m = 0; m < MM; m++){
                const float4* i4 = (const float4*)(ins + slot*576 + m*64);
                float s0=0,s1=0,s2=0,s3=0, d0=0,d1=0,d2=0,d3=0;
                #pragma unroll
                for (int k = 0; k < 16; k++){
                    float4 x = i4[k], a = ws4[k], b = wd4[k];
                    s0 += x.x*a.x; s1 += x.y*a.y; s2 += x.z*a.z; s3 += x.w*a.w;
                    d0 += x.x*b.x; d1 += x.y*b.y; d2 += x.z*b.z; d3 += x.w*b.w;
                }
                float as = (s0+s1)+(s2+s3) + ((m==0)? bss[j] : 0.f);
                float ad = (d0+d1)+(d2+d3);
                g_xs[(size_t)n*576 + m*64 + j] = as;
                g_xd[(size_t)n*576 + m*64 + j] = ad;
            }
        }
    }
}

// ---------------- K2: radial MLP -> w_lc, alpha logits, segment max ------------
__global__ __launch_bounds__(256) void k_edgeA(
    const float* __restrict__ esc, const float* __restrict__ eattr,
    const int* __restrict__ esrc,  const int* __restrict__ edst,
    const float* __restrict__ W1,  const float* __restrict__ b1,
    const float* __restrict__ lng, const float* __restrict__ lnb,
    const float* __restrict__ W2,  const float* __restrict__ off,
    const float* __restrict__ Wa,  const float* __restrict__ ba,
    const float* __restrict__ adot)
{
    extern __shared__ float sm[];
    float* W1T = sm;                   // 64*68
    float* WaT = W1T + 64*68;          // 64*68
    float* W2T = WaT + 64*68;          // 192*68
    float* cb  = W2T + 192*68;         // b1,lng,lnb,ba,adot (5*64) + off(192) = 512
    float* s_s = cb + 512;             // 4*64
    float* s_h = s_s + 256;            // 4*64
    float* s_m = s_h + 256;            // 4*64
    float* s_f = s_m + 256;            // 4*64
    float* s_r = s_f + 256;            // 16
    int tid = threadIdx.x;
    for (int t = tid; t < 4096;  t += 256){ int k = t>>6,  d = t&63;  W1T[d*68+k] = W1[t]; WaT[d*68+k] = Wa[t]; }
    for (int t = tid; t < 12288; t += 256){ int k = t/192, c = t%192; W2T[c*68+k] = W2[t]; }
    if (tid < 64){ cb[tid]=b1[tid]; cb[64+tid]=lng[tid]; cb[128+tid]=lnb[tid]; cb[192+tid]=ba[tid]; cb[256+tid]=adot[tid]; }
    for (int t = tid; t < 192; t += 256) cb[320+t] = off[t];
    __syncthreads();
    int slot = tid>>6, j = tid&63, wid = tid>>5, lane = tid&31;
    for (int base = blockIdx.x*4; base < NE; base += gridDim.x*4){
        int e = base + slot; bool v = e < NE;
        __syncthreads();
        if (v) s_s[slot*64 + j] = esc[(size_t)e*64 + j];
        __syncthreads();
        // hidden layer
        float h;
        {
            const float4* s4 = (const float4*)(s_s + slot*64);
            const float4* w4 = (const float4*)(W1T + j*68);
            float a0=0,a1=0,a2=0,a3=0;
            #pragma unroll
            for (int k = 0; k < 16; k++){
                float4 x = s4[k], w = w4[k];
                a0 += x.x*w.x; a1 += x.y*w.y; a2 += x.z*w.z; a3 += x.w*w.w;
            }
            h = (a0+a1)+(a2+a3) + cb[j];
        }
        // layernorm stats over 64 (two warps per slot)
        float sum = h, sq = h*h;
        #pragma unroll
        for (int o = 16; o > 0; o >>= 1){
            sum += __shfl_xor_sync(0xffffffffu, sum, o);
            sq  += __shfl_xor_sync(0xffffffffu, sq,  o);
        }
        if (lane == 0){ s_r[wid*2] = sum; s_r[wid*2+1] = sq; }
        __syncthreads();
        float ts = s_r[slot*4] + s_r[slot*4+2];
        float tq = s_r[slot*4+1] + s_r[slot*4+3];
        float mu  = ts * (1.f/64.f);
        float var = tq * (1.f/64.f) - mu*mu;
        float hn  = (h - mu) * rsqrtf(var + 1e-5f) * cb[64+j] + cb[128+j];
        float hs  = hn * (1.f/(1.f + __expf(-hn)));   // silu
        s_h[slot*64 + j] = hs;
        __syncthreads();
        // second layer: 3 output rows of w_lc
        float wl0 = 0.f;
        {
            const float4* h4 = (const float4*)(s_h + slot*64);
            #pragma unroll
            for (int r = 0; r < 3; r++){
                const float4* w4 = (const float4*)(W2T + (r*64 + j)*68);
                float a0=0,a1=0,a2=0,a3=0;
                #pragma unroll
                for (int k = 0; k < 16; k++){
                    float4 x = h4[k], w = w4[k];
                    a0 += x.x*w.x; a1 += x.y*w.y; a2 += x.z*w.z; a3 += x.w*w.w;
                }
                float acc = (a0+a1)+(a2+a3) + cb[320 + r*64 + j];
                if (v) g_wlc[(size_t)e*192 + r*64 + j] = acc;
                if (r == 0) wl0 = acc;
            }
        }
        // msg row 0 and alpha logits
        int src = 0, dst = 0; float ea0 = 0.f;
        if (v){ src = esrc[e]; dst = edst[e]; ea0 = eattr[(size_t)e*9]; }
        float m0 = v ? (g_xs[(size_t)src*576 + j] + g_xd[(size_t)dst*576 + j]) * ea0 * wl0 : 0.f;
        s_m[slot*64 + j] = m0;
        __syncthreads();
        float pre;
        {
            const float4* m4 = (const float4*)(s_m + slot*64);
            const float4* w4 = (const float4*)(WaT + j*68);
            float a0=0,a1=0,a2=0,a3=0;
            #pragma unroll
            for (int k = 0; k < 16; k++){
                float4 x = m4[k], w = w4[k];
                a0 += x.x*w.x; a1 += x.y*w.y; a2 += x.z*w.z; a3 += x.w*w.w;
            }
            pre = (a0+a1)+(a2+a3) + cb[192+j];
        }
        float sg = 1.f/(1.f + __expf(-pre));
        float f  = 0.2f*pre + 0.8f*pre*sg;            // smooth_lrelu(a=0.2)
        s_f[slot*64 + j] = f * cb[256+j];             // * alpha_dot[h*8+d]
        __syncthreads();
        if (v && j < 8){
            float lg = 0.f;
            #pragma unroll
            for (int d = 0; d < 8; d++) lg += s_f[slot*64 + j*8 + d];
            g_logit[(size_t)e*8 + j] = lg;
            atomicMax(&g_nmax[dst*8 + j], fkey(lg));
        }
    }
}

// ---------------- K3: value path + weighted segment accumulation ---------------
__global__ __launch_bounds__(256) void k_edgeB(
    const float* __restrict__ eattr, const int* __restrict__ esrc,
    const int* __restrict__ edst,    const float* __restrict__ Wv,
    const float* __restrict__ bv)
{
    extern __shared__ float sm[];
    float* WvvT = sm;                  // 64*68
    float* WvgT = WvvT + 64*68;        // 64*68
    float* bvs  = WvgT + 64*68;        // 128
    float* s_msg= bvs + 128;           // 4*576
    float* s_ea = s_msg + 4*576;       // 4*12
    float* s_w  = s_ea + 48;           // 4*8
    int tid = threadIdx.x;
    for (int t = tid; t < 4096; t += 256){
        int k = t>>6, d = t&63;
        WvvT[d*68+k] = Wv[k*128 + d];
        WvgT[d*68+k] = Wv[k*128 + 64 + d];
    }
    if (tid < 128) bvs[tid] = bv[tid];
    __syncthreads();
    int slot = tid>>6, j = tid&63;
    for (int base = blockIdx.x*4; base < NE; base += gridDim.x*4){
        int e = base + slot; bool v = e < NE;
        __syncthreads();
        int src = 0, dst = 0;
        float wl0 = 0.f, wl1 = 0.f, wl2 = 0.f;
        if (v){
            src = esrc[e]; dst = edst[e];
            wl0 = g_wlc[(size_t)e*192 + j];
            wl1 = g_wlc[(size_t)e*192 + 64 + j];
            wl2 = g_wlc[(size_t)e*192 + 128 + j];
            if (j < 9) s_ea[slot*12 + j] = eattr[(size_t)e*9 + j];
            if (j < 8){
                float lg = g_logit[(size_t)e*8 + j];
                float mx = fdec(g_nmax[dst*8 + j]);
                float w  = __expf(lg - mx);
                s_w[slot*8 + j] = w;
                atomicAdd(&g_denom[dst*8 + j], w);
            }
        }
        __syncthreads();
        if (v){
            #pragma unroll
            for (int m = 0; m < 9; m++){
                float wlm = (m==0) ? wl0 : (m<4) ? wl1 : wl2;
                s_msg[slot*576 + m*64 + j] =
                    (g_xs[(size_t)src*576 + m*64 + j] + g_xd[(size_t)dst*576 + m*64 + j])
                    * s_ea[slot*12 + m] * wlm;
            }
        }
        __syncthreads();
        if (v){
            // gate from msg row 0
            float gs;
            {
                const float4* m4 = (const float4*)(s_msg + slot*576);
                const float4* w4 = (const float4*)(WvgT + j*68);
                float a0=0,a1=0,a2=0,a3=0;
                #pragma unroll
                for (int k = 0; k < 16; k++){
                    float4 x = m4[k], w = w4[k];
                    a0 += x.x*w.x; a1 += x.y*w.y; a2 += x.z*w.z; a3 += x.w*w.w;
                }
                float gvv = (a0+a1)+(a2+a3) + bvs[64+j];
                gs = 1.f/(1.f + __expf(-gvv));
            }
            float wh = s_w[slot*8 + (j>>3)];
            const float4* wv4 = (const float4*)(WvvT + j*68);
            for (int m = 0; m < 9; m++){
                const float4* m4 = (const float4*)(s_msg + slot*576 + m*64);
                float a0=0,a1=0,a2=0,a3=0;
                #pragma unroll
                for (int k = 0; k < 16; k++){
                    float4 x = m4[k], w = wv4[k];
                    a0 += x.x*w.x; a1 += x.y*w.y; a2 += x.z*w.z; a3 += x.w*w.w;
                }
                float acc = (a0+a1)+(a2+a3) + ((m==0) ? bvs[j] : 0.f);
                float val = (m==0) ? acc * (1.f/(1.f + __expf(-acc))) : acc * gs;
                float wlm = (m==0) ? wl0 : (m<4) ? wl1 : wl2;
                val *= s_ea[slot*12 + m] * wlm;
                val *= wh;
                atomicAdd(&g_acc[(size_t)dst*576 + m*64 + j], val);
            }
        }
    }
}

// ---------------- K4: normalize + output projection ----------------------------
__global__ __launch_bounds__(256) void k_out(
    const float* __restrict__ Wp, const float* __restrict__ bp, float* __restrict__ out)
{
    extern __shared__ float sm[];
    float* WpT = sm;                   // 64*68
    float* bps = WpT + 64*68;          // 64
    float* s_y = bps + 64;             // 4*576
    int tid = threadIdx.x;
    for (int t = tid; t < 4096; t += 256){ int k = t>>6, d = t&63; WpT[d*68+k] = Wp[t]; }
    if (tid < 64) bps[tid] = bp[tid];
    __syncthreads();
    int slot = tid>>6, j = tid&63;
    for (int base = blockIdx.x*4; base < NN; base += gridDim.x*4){
        int n = base + slot; bool v = n < NN;
        __syncthreads();
        if (v){
            float dn  = g_denom[n*8 + (j>>3)];
            float inv = 1.f/(dn + 1e-16f);
            #pragma unroll
            for (int m = 0; m < 9; m++)
                s_y[slot*576 + m*64 + j] = g_acc[(size_t)n*576 + m*64 + j] * inv;
        }
        __syncthreads();
        if (v){
            const float4* w4 = (const float4*)(WpT + j*68);
            for (int m = 0; m < 9; m++){
                const float4* y4 = (const float4*)(s_y + slot*576 + m*64);
                float a0=0,a1=0,a2=0,a3=0;
                #pragma unroll
                for (int k = 0; k < 16; k++){
                    float4 x = y4[k], w = w4[k];
                    a0 += x.x*w.x; a1 += x.y*w.y; a2 += x.z*w.z; a3 += x.w*w.w;
                }
                float o = (a0+a1)+(a2+a3) + ((m==0) ? bps[j] : 0.f);
                out[(size_t)n*576 + m*64 + j] = o;
            }
        }
    }
}

extern "C" void kernel_launch(void* const* d_in, const int* in_sizes, int n_in,
                              void* d_out, int out_size)
{
    const float* node_input = (const float*)d_in[0];
    const float* edge_attr  = (const float*)d_in[1];
    const float* edge_scal  = (const float*)d_in[2];
    const float* W_src = (const float*)d_in[3];
    const float* b_src = (const float*)d_in[4];
    const float* W_dst = (const float*)d_in[5];
    const float* rW1   = (const float*)d_in[6];
    const float* rb1   = (const float*)d_in[7];
    const float* lng   = (const float*)d_in[8];
    const float* lnb   = (const float*)d_in[9];
    const float* rW2   = (const float*)d_in[10];
    const float* roff  = (const float*)d_in[11];
    const float* Wa    = (const float*)d_in[12];
    const float* ba    = (const float*)d_in[13];
    const float* adot  = (const float*)d_in[14];
    const float* Wv    = (const float*)d_in[15];
    const float* bv    = (const float*)d_in[16];
    const float* Wp    = (const float*)d_in[17];
    const float* bp    = (const float*)d_in[18];
    const int*   esrc  = (const int*)d_in[19];
    const int*   edst  = (const int*)d_in[20];
    float* out = (float*)d_out;

    const int smem1 = (64*68*2 + 64 + 4*576) * 4;                         // 44288
    const int smem2 = (64*68*2 + 192*68 + 512 + 4*256 + 16) * 4;          // 93248
    const int smem3 = (64*68*2 + 128 + 4*576 + 48 + 32) * 4;              // 44864
    const int smem4 = (64*68 + 64 + 4*576) * 4;                           // 26880

    cudaFuncSetAttribute(k_node,  cudaFuncAttributeMaxDynamicSharedMemorySize, smem1);
    cudaFuncSetAttribute(k_edgeA, cudaFuncAttributeMaxDynamicSharedMemorySize, smem2);
    cudaFuncSetAttribute(k_edgeB, cudaFuncAttributeMaxDynamicSharedMemorySize, smem3);
    cudaFuncSetAttribute(k_out,   cudaFuncAttributeMaxDynamicSharedMemorySize, smem4);

    k_init<<<2048, 256>>>();
    k_node<<<296, 256, smem1>>>(node_input, W_src, b_src, W_dst);
    k_edgeA<<<296, 256, smem2>>>(edge_scal, edge_attr, esrc, edst,
                                 rW1, rb1, lng, lnb, rW2, roff, Wa, ba, adot);
    k_edgeB<<<592, 256, smem3>>>(edge_attr, esrc, edst, Wv, bv);
    k_out<<<296, 256, smem4>>>(Wp, bp, out);
}

// round 2
// speedup vs baseline: 1.3324x; 1.3324x over previous
#include <cuda_runtime.h>
#include <math.h>

#define NN 10000
#define NE 160000
#define MM 9
#define CC 64
#define HH 8

// ---------------- scratch (static device globals; no allocation) ----------------
__device__ float    g_xs[NN*MM*CC];        // node src-linear   (23 MB)
__device__ float    g_xd[NN*MM*CC];        // node dst-linear   (23 MB)
__device__ float    g_wlc[(size_t)NE*192]; // radial weights    (123 MB)
__device__ float    g_logit[NE*HH];
__device__ unsigned g_nmax[NN*HH];         // monotone-mapped float max
__device__ float    g_denom[NN*HH];
__device__ float    g_acc[NN*MM*CC];

__device__ __forceinline__ unsigned fkey(float f){
    int i = __float_as_int(f);
    return (i >= 0) ? ((unsigned)i ^ 0x80000000u) : ~(unsigned)i;
}
__device__ __forceinline__ float fdec(unsigned u){
    int i = (u & 0x80000000u) ? (int)(u ^ 0x80000000u) : (int)(~u);
    return __int_as_float(i);
}
__device__ __forceinline__ float sigf(float x){ return 1.f/(1.f + __expf(-x)); }

__global__ void k_init(){
    int i = blockIdx.x*blockDim.x + threadIdx.x;
    int st = gridDim.x*blockDim.x;
    for (int t = i; t < NN*MM*CC; t += st) g_acc[t] = 0.f;
    for (int t = i; t < NN*HH;    t += st){ g_denom[t] = 0.f; g_nmax[t] = fkey(-INFINITY); }
}

// ================= K1: node linear (GEMM: 4 nodes -> X[40x64] @ W[64x128]) =====
__global__ __launch_bounds__(256) void k_node(
    const float* __restrict__ xin, const float* __restrict__ Ws,
    const float* __restrict__ bs,  const float* __restrict__ Wd)
{
    extern __shared__ float sm[];
    float* s_W = sm;               // [64][128]  col 0-63: Ws, 64-127: Wd
    float* s_X = s_W + 64*128;     // [40][68]
    float* s_b = s_X + 40*68;      // 64
    int tid = threadIdx.x;
    for (int t = tid; t < 8192; t += 256){
        int k = t>>7, c = t&127;
        s_W[t] = (c < 64) ? Ws[k*64 + c] : Wd[k*64 + (c-64)];
    }
    if (tid < 64) s_b[tid] = bs[tid];
    // pad rows 36..39
    for (int t = tid; t < 4*68; t += 256) s_X[36*68 + t] = 0.f;
    __syncthreads();

    int rg = tid>>5;              // 0..7  -> rows rg*5..rg*5+4
    int c0 = (tid&31)*4;          // 0..124
    int r0 = rg*5;

    for (int base = blockIdx.x*4; base < NN; base += gridDim.x*4){
        __syncthreads();
        for (int i = tid; i < 4*576; i += 256){
            int n = i/576, rem = i - n*576;
            int row = n*9 + (rem>>6), col = rem&63;
            s_X[row*68 + col] = xin[(size_t)(base+n)*576 + rem];
        }
        __syncthreads();
        float4 a0 = {0,0,0,0}, a1 = a0, a2 = a0, a3 = a0, a4 = a0;
        const float* Xp = s_X + r0*68;
        #pragma unroll 8
        for (int k = 0; k < 64; k++){
            float4 w = *(const float4*)(s_W + k*128 + c0);
            float x0 = Xp[k], x1 = Xp[68+k], x2 = Xp[136+k], x3 = Xp[204+k], x4 = Xp[272+k];
            a0.x += x0*w.x; a0.y += x0*w.y; a0.z += x0*w.z; a0.w += x0*w.w;
            a1.x += x1*w.x; a1.y += x1*w.y; a1.z += x1*w.z; a1.w += x1*w.w;
            a2.x += x2*w.x; a2.y += x2*w.y; a2.z += x2*w.z; a2.w += x2*w.w;
            a3.x += x3*w.x; a3.y += x3*w.y; a3.z += x3*w.z; a3.w += x3*w.w;
            a4.x += x4*w.x; a4.y += x4*w.y; a4.z += x4*w.z; a4.w += x4*w.w;
        }
        float4 acc[5] = {a0,a1,a2,a3,a4};
        #pragma unroll
        for (int i = 0; i < 5; i++){
            int r = r0 + i;
            if (r < 36){
                int n = base + r/9, m = r%9;
                float4 v = acc[i];
                if (m == 0 && c0 < 64){
                    v.x += s_b[c0]; v.y += s_b[c0+1]; v.z += s_b[c0+2]; v.w += s_b[c0+3];
                }
                if (c0 < 64) *(float4*)(g_xs + (size_t)n*576 + m*64 + c0) = v;
                else         *(float4*)(g_xd + (size_t)n*576 + m*64 + (c0-64)) = v;
            }
        }
    }
}

// ================= K2: radial MLP + alpha logits (16 edges/iter) ================
__global__ __launch_bounds__(256) void k_edgeA(
    const float* __restrict__ esc, const float* __restrict__ eattr,
    const int* __restrict__ esrc,  const int* __restrict__ edst,
    const float* __restrict__ W1,  const float* __restrict__ b1,
    const float* __restrict__ lng, const float* __restrict__ lnb,
    const float* __restrict__ W2,  const float* __restrict__ off,
    const float* __restrict__ Wa,  const float* __restrict__ ba,
    const float* __restrict__ adot)
{
    extern __shared__ float sm[];
    float* s_W1 = sm;               // [64][68]
    float* s_Wa = s_W1 + 64*68;     // [64][68]
    float* s_W2 = s_Wa + 64*68;     // [64][192] raw
    float* cb   = s_W2 + 64*192;    // b1|lng|lnb|ba|adot|off  = 512
    float* s_S  = cb + 512;         // [16][68]
    float* s_H  = s_S + 16*68;      // [16][68]
    float* s_M0 = s_H + 16*68;      // [16][68]
    float* s_WL = s_M0 + 16*68;     // [16][192]
    int tid = threadIdx.x;
    for (int t = tid; t < 4096; t += 256){
        int k = t>>6, j = t&63;
        s_W1[k*68+j] = W1[t]; s_Wa[k*68+j] = Wa[t];
    }
    for (int t = tid; t < 12288; t += 256) s_W2[t] = W2[t];
    if (tid < 64){
        cb[tid] = b1[tid]; cb[64+tid] = lng[tid]; cb[128+tid] = lnb[tid];
        cb[192+tid] = ba[tid]; cb[256+tid] = adot[tid];
    }
    for (int t = tid; t < 192; t += 256) cb[320+t] = off[t];
    __syncthreads();

    int rg = tid>>4;            // 0..15 (edge row)
    int tx = tid&15;
    int c0 = tx*4;

    for (int base = blockIdx.x*16; base < NE; base += gridDim.x*16){
        __syncthreads();
        // phase 1: load scalars
        for (int i = tid; i < 16*64; i += 256){
            int e = i>>6, c = i&63;
            s_S[e*68 + c] = esc[(size_t)(base+e)*64 + c];
        }
        __syncthreads();
        // GEMM1: H = S @ W1  (1 row x 4 cols per thread)
        {
            float4 a = {0,0,0,0};
            const float* Xp = s_S + rg*68;
            #pragma unroll 8
            for (int k = 0; k < 64; k++){
                float x = Xp[k];
                float4 w = *(const float4*)(s_W1 + k*68 + c0);
                a.x += x*w.x; a.y += x*w.y; a.z += x*w.z; a.w += x*w.w;
            }
            a.x += cb[c0]; a.y += cb[c0+1]; a.z += cb[c0+2]; a.w += cb[c0+3];
            // LN across the 16 threads owning this row
            float s = a.x+a.y+a.z+a.w;
            float q = a.x*a.x+a.y*a.y+a.z*a.z+a.w*a.w;
            #pragma unroll
            for (int o = 8; o > 0; o >>= 1){
                s += __shfl_xor_sync(0xffffffffu, s, o);
                q += __shfl_xor_sync(0xffffffffu, q, o);
            }
            float mu = s*(1.f/64.f);
            float var = q*(1.f/64.f) - mu*mu;
            float rs = rsqrtf(var + 1e-5f);
            float4 h;
            h.x = (a.x-mu)*rs*cb[64+c0  ] + cb[128+c0  ];
            h.y = (a.y-mu)*rs*cb[64+c0+1] + cb[128+c0+1];
            h.z = (a.z-mu)*rs*cb[64+c0+2] + cb[128+c0+2];
            h.w = (a.w-mu)*rs*cb[64+c0+3] + cb[128+c0+3];
            h.x *= sigf(h.x); h.y *= sigf(h.y); h.z *= sigf(h.z); h.w *= sigf(h.w);
            *(float4*)(s_H + rg*68 + c0) = h;
        }
        __syncthreads();
        // GEMM2: WL = H @ W2  (4 rows x 3 cols per thread)
        {
            int rgr = tid>>6;           // 0..3 -> rows rgr, rgr+4, rgr+8, rgr+12
            int cc  = tid&63;
            float acc[4][3] = {{0,0,0},{0,0,0},{0,0,0},{0,0,0}};
            #pragma unroll 4
            for (int k = 0; k < 64; k++){
                float x0 = s_H[(rgr   )*68 + k];
                float x1 = s_H[(rgr+4 )*68 + k];
                float x2 = s_H[(rgr+8 )*68 + k];
                float x3 = s_H[(rgr+12)*68 + k];
                float w0 = s_W2[k*192 + cc];
                float w1 = s_W2[k*192 + cc + 64];
                float w2 = s_W2[k*192 + cc + 128];
                acc[0][0]+=x0*w0; acc[0][1]+=x0*w1; acc[0][2]+=x0*w2;
                acc[1][0]+=x1*w0; acc[1][1]+=x1*w1; acc[1][2]+=x1*w2;
                acc[2][0]+=x2*w0; acc[2][1]+=x2*w1; acc[2][2]+=x2*w2;
                acc[3][0]+=x3*w0; acc[3][1]+=x3*w1; acc[3][2]+=x3*w2;
            }
            #pragma unroll
            for (int i = 0; i < 4; i++){
                int r = rgr + i*4;
                #pragma unroll
                for (int j = 0; j < 3; j++){
                    float v = acc[i][j] + cb[320 + cc + 64*j];
                    s_WL[r*192 + cc + 64*j] = v;
                    g_wlc[(size_t)(base+r)*192 + cc + 64*j] = v;
                }
            }
        }
        __syncthreads();
        // M0 build: msg row0 = (xs0+xd0)*ea0*wl0
        int dst;
        {
            int e = rg;
            int src = esrc[base+e]; dst = edst[base+e];
            float ea0 = eattr[(size_t)(base+e)*9];
            float4 xs = *(const float4*)(g_xs + (size_t)src*576 + c0);
            float4 xd = *(const float4*)(g_xd + (size_t)dst*576 + c0);
            float4 wl = *(const float4*)(s_WL + e*192 + c0);
            float4 m0;
            m0.x = (xs.x+xd.x)*ea0*wl.x; m0.y = (xs.y+xd.y)*ea0*wl.y;
            m0.z = (xs.z+xd.z)*ea0*wl.z; m0.w = (xs.w+xd.w)*ea0*wl.w;
            *(float4*)(s_M0 + e*68 + c0) = m0;
        }
        __syncthreads();
        // GEMM3: A = M0 @ Wa, smooth_lrelu, dot alpha_dot, logits
        {
            float4 a = {0,0,0,0};
            const float* Xp = s_M0 + rg*68;
            #pragma unroll 8
            for (int k = 0; k < 64; k++){
                float x = Xp[k];
                float4 w = *(const float4*)(s_Wa + k*68 + c0);
                a.x += x*w.x; a.y += x*w.y; a.z += x*w.z; a.w += x*w.w;
            }
            a.x += cb[192+c0]; a.y += cb[192+c0+1]; a.z += cb[192+c0+2]; a.w += cb[192+c0+3];
            a.x = 0.2f*a.x + 0.8f*a.x*sigf(a.x);
            a.y = 0.2f*a.y + 0.8f*a.y*sigf(a.y);
            a.z = 0.2f*a.z + 0.8f*a.z*sigf(a.z);
            a.w = 0.2f*a.w + 0.8f*a.w*sigf(a.w);
            float s4 = a.x*cb[256+c0] + a.y*cb[256+c0+1] + a.z*cb[256+c0+2] + a.w*cb[256+c0+3];
            float lg = s4 + __shfl_xor_sync(0xffffffffu, s4, 1);
            if ((tx & 1) == 0){
                int h = tx >> 1;
                g_logit[(size_t)(base+rg)*8 + h] = lg;
                atomicMax(&g_nmax[dst*8 + h], fkey(lg));
            }
        }
    }
}

// ================= K3: value GEMM + weighted scatter (8 edges/iter) =============
__global__ __launch_bounds__(256) void k_edgeB(
    const float* __restrict__ eattr, const int* __restrict__ esrc,
    const int* __restrict__ edst,    const float* __restrict__ Wv,
    const float* __restrict__ bv)
{
    extern __shared__ float sm[];
    float* s_W  = sm;                // [64][128] raw Wv
    float* s_X  = s_W + 64*128;      // [80][68]  (also reused as Y)
    float* s_wl = s_X + 80*68;       // [8][192]
    float* s_ea = s_wl + 8*192;      // [8][12]
    float* s_w  = s_ea + 96;         // [8][8]
    float* s_bv = s_w + 64;          // 128
    int*   s_dst = (int*)(s_bv + 128); // 8
    int tid = threadIdx.x;
    for (int t = tid; t < 8192; t += 256) s_W[t] = Wv[t];
    if (tid < 128) s_bv[tid] = bv[tid];
    __syncthreads();

    int rg = tid>>4;                 // 0..15
    int tx = tid&15;
    int c0 = tx*4;
    int r0 = rg*5;
    bool odd = (rg & 1);
    int sel4 = c0 + (odd ? 64 : 0);  // row r0+4 weight col base
    int wid = tid>>5, lane = tid&31;

    for (int base = blockIdx.x*8; base < NE; base += gridDim.x*8){
        __syncthreads();
        // phase 1: per-edge metadata
        for (int i = tid; i < 8*192; i += 256) s_wl[i] = g_wlc[(size_t)base*192 + i];
        if (tid < 72){
            int e = tid/9, m = tid - e*9;
            s_ea[e*12 + m] = eattr[(size_t)(base+e)*9 + m];
        }
        if (tid < 8) s_dst[tid] = edst[base + tid];
        if (tid >= 128 && tid < 192){
            int t2 = tid - 128;
            int e = t2>>3, h = t2&7;
            int d = edst[base + e];
            float lg = g_logit[(size_t)(base+e)*8 + h];
            float mx = fdec(g_nmax[d*8 + h]);
            float w = __expf(lg - mx);
            s_w[e*8 + h] = w;
            atomicAdd(&g_denom[d*8 + h], w);
        }
        __syncthreads();
        // phase 2: build X (warp w -> edge w)
        {
            int e = wid;
            int src = esrc[base+e];
            int d   = s_dst[e];
            const float2* xs = (const float2*)(g_xs + (size_t)src*576);
            const float2* xd = (const float2*)(g_xd + (size_t)d*576);
            float2 row0v;
            #pragma unroll
            for (int m = 0; m < 9; m++){
                float2 a = xs[m*32 + lane];
                float2 b = xd[m*32 + lane];
                float eam = s_ea[e*12 + m];
                int l = (m==0) ? 0 : (m<4) ? 1 : 2;
                float2 wl = *(const float2*)(s_wl + e*192 + l*64 + 2*lane);
                float2 v;
                v.x = (a.x+b.x)*eam*wl.x;
                v.y = (a.y+b.y)*eam*wl.y;
                *(float2*)(s_X + (e*10+m)*68 + 2*lane) = v;
                if (m == 0) row0v = v;
            }
            *(float2*)(s_X + (e*10+9)*68 + 2*lane) = row0v;  // gate row = row0
        }
        __syncthreads();
        // phase 3: GEMM  Y[80x64] : rows r0..r0+3 value cols, row r0+4 value/gate
        float4 a0 = {0,0,0,0}, a1 = a0, a2 = a0, a3 = a0, a4 = a0;
        {
            const float* Xp = s_X + r0*68;
            #pragma unroll 8
            for (int k = 0; k < 64; k++){
                float4 wv = *(const float4*)(s_W + k*128 + c0);
                float4 w4 = *(const float4*)(s_W + k*128 + sel4);
                float x0 = Xp[k], x1 = Xp[68+k], x2 = Xp[136+k], x3 = Xp[204+k], x4 = Xp[272+k];
                a0.x += x0*wv.x; a0.y += x0*wv.y; a0.z += x0*wv.z; a0.w += x0*wv.w;
                a1.x += x1*wv.x; a1.y += x1*wv.y; a1.z += x1*wv.z; a1.w += x1*wv.w;
                a2.x += x2*wv.x; a2.y += x2*wv.y; a2.z += x2*wv.z; a2.w += x2*wv.w;
                a3.x += x3*wv.x; a3.y += x3*wv.y; a3.z += x3*wv.z; a3.w += x3*wv.w;
                a4.x += x4*w4.x; a4.y += x4*w4.y; a4.z += x4*w4.z; a4.w += x4*w4.w;
            }
        }
        __syncthreads();   // all X reads done; reuse s_X as Y
        {
            // bias: row r%10==0 (even rg, i=0): value bias; r%10==9 (odd rg, i=4): gate bias
            if (!odd){
                a0.x += s_bv[c0]; a0.y += s_bv[c0+1]; a0.z += s_bv[c0+2]; a0.w += s_bv[c0+3];
            } else {
                a4.x += s_bv[64+c0]; a4.y += s_bv[64+c0+1]; a4.z += s_bv[64+c0+2]; a4.w += s_bv[64+c0+3];
            }
            *(float4*)(s_X + (r0  )*68 + c0) = a0;
            *(float4*)(s_X + (r0+1)*68 + c0) = a1;
            *(float4*)(s_X + (r0+2)*68 + c0) = a2;
            *(float4*)(s_X + (r0+3)*68 + c0) = a3;
            *(float4*)(s_X + (r0+4)*68 + c0) = a4;
        }
        __syncthreads();
        // phase 4: postprocess + scatter  (2 edges per thread)
        #pragma unroll
        for (int pass = 0; pass < 2; pass++){
            int e = (tid>>6) + pass*4;
            int j = tid&63;
            float gate = sigf(s_X[(e*10+9)*68 + j]);
            float wh = s_w[e*8 + (j>>3)];
            int d = s_dst[e];
            float* accp = g_acc + (size_t)d*576 + j;
            #pragma unroll
            for (int m = 0; m < 9; m++){
                float y = s_X[(e*10+m)*68 + j];
                float val = (m==0) ? y*sigf(y) : y*gate;
                int l = (m==0) ? 0 : (m<4) ? 1 : 2;
                val *= s_ea[e*12+m] * s_wl[e*192 + l*64 + j] * wh;
                atomicAdd(accp + m*64, val);
            }
        }
    }
}

// ================= K4: normalize + projection (8 nodes/iter) ====================
__global__ __launch_bounds__(256) void k_out(
    const float* __restrict__ Wp, const float* __restrict__ bp, float* __restrict__ out)
{
    extern __shared__ float sm[];
    float* s_W  = sm;              // [64][68]
    float* s_X  = s_W + 64*68;     // [80][68]
    float* s_b  = s_X + 80*68;     // 64
    float* s_inv= s_b + 64;        // 64
    int tid = threadIdx.x;
    for (int t = tid; t < 4096; t += 256){
        int k = t>>6, j = t&63;
        s_W[k*68 + j] = Wp[t];
    }
    if (tid < 64) s_b[tid] = bp[tid];
    for (int t = tid; t < 8*68; t += 256) s_X[72*68 + t] = 0.f;
    __syncthreads();

    int rg = tid>>4, tx = tid&15, c0 = tx*4, r0 = rg*5;

    for (int base = blockIdx.x*8; base < NN; base += gridDim.x*8){
        __syncthreads();
        if (tid < 64){
            int e = tid>>3, h = tid&7;
            s_inv[tid] = 1.f/(g_denom[(base+e)*8 + h] + 1e-16f);
        }
        __syncthreads();
        for (int i = tid; i < 8*576; i += 256){
            int n = i/576, rem = i - n*576;
            int row = n*9 + (rem>>6), col = rem&63;
            s_X[row*68 + col] = g_acc[(size_t)(base+n)*576 + rem] * s_inv[n*8 + (col>>3)];
        }
        __syncthreads();
        float4 a0 = {0,0,0,0}, a1 = a0, a2 = a0, a3 = a0, a4 = a0;
        const float* Xp = s_X + r0*68;
        #pragma unroll 8
        for (int k = 0; k < 64; k++){
            float4 w = *(const float4*)(s_W + k*68 + c0);
            float x0 = Xp[k], x1 = Xp[68+k], x2 = Xp[136+k], x3 = Xp[204+k], x4 = Xp[272+k];
            a0.x += x0*w.x; a0.y += x0*w.y; a0.z += x0*w.z; a0.w += x0*w.w;
            a1.x += x1*w.x; a1.y += x1*w.y; a1.z += x1*w.z; a1.w += x1*w.w;
            a2.x += x2*w.x; a2.y += x2*w.y; a2.z += x2*w.z; a2.w += x2*w.w;
            a3.x += x3*w.x; a3.y += x3*w.y; a3.z += x3*w.z; a3.w += x3*w.w;
            a4.x += x4*w.x; a4.y += x4*w.y; a4.z += x4*w.z; a4.w += x4*w.w;
        }
        float4 acc[5] = {a0,a1,a2,a3,a4};
        #pragma unroll
        for (int i = 0; i < 5; i++){
            int r = r0 + i;
            if (r < 72){
                int n = base + r/9, m = r%9;
                float4 v = acc[i];
                if (m == 0){
                    v.x += s_b[c0]; v.y += s_b[c0+1]; v.z += s_b[c0+2]; v.w += s_b[c0+3];
                }
                *(float4*)(out + (size_t)n*576 + m*64 + c0) = v;
            }
        }
    }
}

extern "C" void kernel_launch(void* const* d_in, const int* in_sizes, int n_in,
                              void* d_out, int out_size)
{
    const float* node_input = (const float*)d_in[0];
    const float* edge_attr  = (const float*)d_in[1];
    const float* edge_scal  = (const float*)d_in[2];
    const float* W_src = (const float*)d_in[3];
    const float* b_src = (const float*)d_in[4];
    const float* W_dst = (const float*)d_in[5];
    const float* rW1   = (const float*)d_in[6];
    const float* rb1   = (const float*)d_in[7];
    const float* lng   = (const float*)d_in[8];
    const float* lnb   = (const float*)d_in[9];
    const float* rW2   = (const float*)d_in[10];
    const float* roff  = (const float*)d_in[11];
    const float* Wa    = (const float*)d_in[12];
    const float* ba    = (const float*)d_in[13];
    const float* adot  = (const float*)d_in[14];
    const float* Wv    = (const float*)d_in[15];
    const float* bv    = (const float*)d_in[16];
    const float* Wp    = (const float*)d_in[17];
    const float* bp    = (const float*)d_in[18];
    const int*   esrc  = (const int*)d_in[19];
    const int*   edst  = (const int*)d_in[20];
    float* out = (float*)d_out;

    const int smem_node = (64*128 + 40*68 + 64) * 4;
    const int smem_eA   = (64*68*2 + 64*192 + 512 + 16*68*3 + 16*192) * 4;
    const int smem_eB   = (64*128 + 80*68 + 8*192 + 96 + 64 + 128 + 8) * 4;
    const int smem_out  = (64*68 + 80*68 + 64 + 64) * 4;

    cudaFuncSetAttribute(k_node,  cudaFuncAttributeMaxDynamicSharedMemorySize, smem_node);
    cudaFuncSetAttribute(k_edgeA, cudaFuncAttributeMaxDynamicSharedMemorySize, smem_eA);
    cudaFuncSetAttribute(k_edgeB, cudaFuncAttributeMaxDynamicSharedMemorySize, smem_eB);
    cudaFuncSetAttribute(k_out,   cudaFuncAttributeMaxDynamicSharedMemorySize, smem_out);

    k_init<<<2048, 256>>>();
    k_node<<<296, 256, smem_node>>>(node_input, W_src, b_src, W_dst);
    k_edgeA<<<148, 256, smem_eA>>>(edge_scal, edge_attr, esrc, edst,
                                   rW1, rb1, lng, lnb, rW2, roff, Wa, ba, adot);
    k_edgeB<<<296, 256, smem_eB>>>(edge_attr, esrc, edst, Wv, bv);
    k_out<<<296, 256, smem_out>>>(Wp, bp, out);
}

// round 3
// speedup vs baseline: 1.8867x; 1.4160x over previous
#include <cuda_runtime.h>
#include <math.h>

#define NN 10000
#define NE 160000
#define MM 9
#define CC 64
#define HH 8

// ---------------- scratch (static device globals; no allocation) ----------------
__device__ float    g_xs[NN*MM*CC];        // node src-linear   (23 MB)
__device__ float    g_xd[NN*MM*CC];        // node dst-linear   (23 MB)
__device__ float    g_wlc[(size_t)NE*192]; // radial weights    (123 MB)
__device__ float    g_logit[NE*HH];
__device__ unsigned g_nmax[NN*HH];         // monotone-mapped float max
__device__ float    g_denom[NN*HH];
__device__ float    g_acc[NN*MM*CC];

__device__ __forceinline__ unsigned fkey(float f){
    int i = __float_as_int(f);
    return (i >= 0) ? ((unsigned)i ^ 0x80000000u) : ~(unsigned)i;
}
__device__ __forceinline__ float fdec(unsigned u){
    int i = (u & 0x80000000u) ? (int)(u ^ 0x80000000u) : (int)(~u);
    return __int_as_float(i);
}
__device__ __forceinline__ float sigf(float x){ return 1.f/(1.f + __expf(-x)); }

__global__ void k_init(){
    int i = blockIdx.x*blockDim.x + threadIdx.x;
    int st = gridDim.x*blockDim.x;
    for (int t = i; t < NN*MM*CC; t += st) g_acc[t] = 0.f;
    for (int t = i; t < NN*HH;    t += st){ g_denom[t] = 0.f; g_nmax[t] = fkey(-INFINITY); }
}

// ================= K1: node linear (GEMM: 4 nodes -> X[40x64] @ W[64x128]) =====
__global__ __launch_bounds__(256) void k_node(
    const float* __restrict__ xin, const float* __restrict__ Ws,
    const float* __restrict__ bs,  const float* __restrict__ Wd)
{
    extern __shared__ float sm[];
    float* s_W = sm;               // [64][128]  col 0-63: Ws, 64-127: Wd
    float* s_X = s_W + 64*128;     // [40][68]
    float* s_b = s_X + 40*68;      // 64
    int tid = threadIdx.x;
    for (int t = tid; t < 8192; t += 256){
        int k = t>>7, c = t&127;
        s_W[t] = (c < 64) ? Ws[k*64 + c] : Wd[k*64 + (c-64)];
    }
    if (tid < 64) s_b[tid] = bs[tid];
    for (int t = tid; t < 4*68; t += 256) s_X[36*68 + t] = 0.f;
    __syncthreads();

    int rg = tid>>5;              // 0..7  -> rows rg*5..rg*5+4
    int c0 = (tid&31)*4;          // 0..124
    int r0 = rg*5;

    for (int base = blockIdx.x*4; base < NN; base += gridDim.x*4){
        __syncthreads();
        for (int i = tid; i < 4*576; i += 256){
            int n = i/576, rem = i - n*576;
            int row = n*9 + (rem>>6), col = rem&63;
            s_X[row*68 + col] = xin[(size_t)(base+n)*576 + rem];
        }
        __syncthreads();
        float4 a0 = {0,0,0,0}, a1 = a0, a2 = a0, a3 = a0, a4 = a0;
        const float* Xp = s_X + r0*68;
        #pragma unroll 8
        for (int k = 0; k < 64; k++){
            float4 w = *(const float4*)(s_W + k*128 + c0);
            float x0 = Xp[k], x1 = Xp[68+k], x2 = Xp[136+k], x3 = Xp[204+k], x4 = Xp[272+k];
            a0.x += x0*w.x; a0.y += x0*w.y; a0.z += x0*w.z; a0.w += x0*w.w;
            a1.x += x1*w.x; a1.y += x1*w.y; a1.z += x1*w.z; a1.w += x1*w.w;
            a2.x += x2*w.x; a2.y += x2*w.y; a2.z += x2*w.z; a2.w += x2*w.w;
            a3.x += x3*w.x; a3.y += x3*w.y; a3.z += x3*w.z; a3.w += x3*w.w;
            a4.x += x4*w.x; a4.y += x4*w.y; a4.z += x4*w.z; a4.w += x4*w.w;
        }
        float4 acc[5] = {a0,a1,a2,a3,a4};
        #pragma unroll
        for (int i = 0; i < 5; i++){
            int r = r0 + i;
            if (r < 36){
                int n = base + r/9, m = r%9;
                float4 v = acc[i];
                if (m == 0 && c0 < 64){
                    v.x += s_b[c0]; v.y += s_b[c0+1]; v.z += s_b[c0+2]; v.w += s_b[c0+3];
                }
                if (c0 < 64) *(float4*)(g_xs + (size_t)n*576 + m*64 + c0) = v;
                else         *(float4*)(g_xd + (size_t)n*576 + m*64 + (c0-64)) = v;
            }
        }
    }
}

// ================= K2: radial MLP + alpha logits (16 edges/iter) ================
__global__ __launch_bounds__(256) void k_edgeA(
    const float* __restrict__ esc, const float* __restrict__ eattr,
    const int* __restrict__ esrc,  const int* __restrict__ edst,
    const float* __restrict__ W1,  const float* __restrict__ b1,
    const float* __restrict__ lng, const float* __restrict__ lnb,
    const float* __restrict__ W2,  const float* __restrict__ off,
    const float* __restrict__ Wa,  const float* __restrict__ ba,
    const float* __restrict__ adot)
{
    extern __shared__ float sm[];
    float* s_W1 = sm;               // [64][68]
    float* s_Wa = s_W1 + 64*68;     // [64][68]
    float* s_W2 = s_Wa + 64*68;     // [64][192] raw
    float* cb   = s_W2 + 64*192;    // b1|lng|lnb|ba|adot|off  = 512
    float* s_S  = cb + 512;         // [16][68]
    float* s_H  = s_S + 16*68;      // [16][68]
    float* s_M0 = s_H + 16*68;      // [16][68]
    float* s_WL = s_M0 + 16*68;     // [16][192]
    int tid = threadIdx.x;
    for (int t = tid; t < 4096; t += 256){
        int k = t>>6, j = t&63;
        s_W1[k*68+j] = W1[t]; s_Wa[k*68+j] = Wa[t];
    }
    for (int t = tid; t < 12288; t += 256) s_W2[t] = W2[t];
    if (tid < 64){
        cb[tid] = b1[tid]; cb[64+tid] = lng[tid]; cb[128+tid] = lnb[tid];
        cb[192+tid] = ba[tid]; cb[256+tid] = adot[tid];
    }
    for (int t = tid; t < 192; t += 256) cb[320+t] = off[t];
    __syncthreads();

    int rg = tid>>4;            // 0..15 (edge row)
    int tx = tid&15;
    int c0 = tx*4;

    for (int base = blockIdx.x*16; base < NE; base += gridDim.x*16){
        __syncthreads();
        for (int i = tid; i < 16*64; i += 256){
            int e = i>>6, c = i&63;
            s_S[e*68 + c] = esc[(size_t)(base+e)*64 + c];
        }
        __syncthreads();
        // GEMM1: H = S @ W1
        {
            float4 a = {0,0,0,0};
            const float* Xp = s_S + rg*68;
            #pragma unroll 8
            for (int k = 0; k < 64; k++){
                float x = Xp[k];
                float4 w = *(const float4*)(s_W1 + k*68 + c0);
                a.x += x*w.x; a.y += x*w.y; a.z += x*w.z; a.w += x*w.w;
            }
            a.x += cb[c0]; a.y += cb[c0+1]; a.z += cb[c0+2]; a.w += cb[c0+3];
            float s = a.x+a.y+a.z+a.w;
            float q = a.x*a.x+a.y*a.y+a.z*a.z+a.w*a.w;
            #pragma unroll
            for (int o = 8; o > 0; o >>= 1){
                s += __shfl_xor_sync(0xffffffffu, s, o);
                q += __shfl_xor_sync(0xffffffffu, q, o);
            }
            float mu = s*(1.f/64.f);
            float var = q*(1.f/64.f) - mu*mu;
            float rs = rsqrtf(var + 1e-5f);
            float4 h;
            h.x = (a.x-mu)*rs*cb[64+c0  ] + cb[128+c0  ];
            h.y = (a.y-mu)*rs*cb[64+c0+1] + cb[128+c0+1];
            h.z = (a.z-mu)*rs*cb[64+c0+2] + cb[128+c0+2];
            h.w = (a.w-mu)*rs*cb[64+c0+3] + cb[128+c0+3];
            h.x *= sigf(h.x); h.y *= sigf(h.y); h.z *= sigf(h.z); h.w *= sigf(h.w);
            *(float4*)(s_H + rg*68 + c0) = h;
        }
        __syncthreads();
        // GEMM2: WL = H @ W2
        {
            int rgr = tid>>6;
            int cc  = tid&63;
            float acc[4][3] = {{0,0,0},{0,0,0},{0,0,0},{0,0,0}};
            #pragma unroll 4
            for (int k = 0; k < 64; k++){
                float x0 = s_H[(rgr   )*68 + k];
                float x1 = s_H[(rgr+4 )*68 + k];
                float x2 = s_H[(rgr+8 )*68 + k];
                float x3 = s_H[(rgr+12)*68 + k];
                float w0 = s_W2[k*192 + cc];
                float w1 = s_W2[k*192 + cc + 64];
                float w2 = s_W2[k*192 + cc + 128];
                acc[0][0]+=x0*w0; acc[0][1]+=x0*w1; acc[0][2]+=x0*w2;
                acc[1][0]+=x1*w0; acc[1][1]+=x1*w1; acc[1][2]+=x1*w2;
                acc[2][0]+=x2*w0; acc[2][1]+=x2*w1; acc[2][2]+=x2*w2;
                acc[3][0]+=x3*w0; acc[3][1]+=x3*w1; acc[3][2]+=x3*w2;
            }
            #pragma unroll
            for (int i = 0; i < 4; i++){
                int r = rgr + i*4;
                #pragma unroll
                for (int j = 0; j < 3; j++){
                    float v = acc[i][j] + cb[320 + cc + 64*j];
                    s_WL[r*192 + cc + 64*j] = v;
                    g_wlc[(size_t)(base+r)*192 + cc + 64*j] = v;
                }
            }
        }
        __syncthreads();
        // M0 build
        int dst;
        {
            int e = rg;
            int src = esrc[base+e]; dst = edst[base+e];
            float ea0 = eattr[(size_t)(base+e)*9];
            float4 xs = *(const float4*)(g_xs + (size_t)src*576 + c0);
            float4 xd = *(const float4*)(g_xd + (size_t)dst*576 + c0);
            float4 wl = *(const float4*)(s_WL + e*192 + c0);
            float4 m0;
            m0.x = (xs.x+xd.x)*ea0*wl.x; m0.y = (xs.y+xd.y)*ea0*wl.y;
            m0.z = (xs.z+xd.z)*ea0*wl.z; m0.w = (xs.w+xd.w)*ea0*wl.w;
            *(float4*)(s_M0 + e*68 + c0) = m0;
        }
        __syncthreads();
        // GEMM3: alpha logits
        {
            float4 a = {0,0,0,0};
            const float* Xp = s_M0 + rg*68;
            #pragma unroll 8
            for (int k = 0; k < 64; k++){
                float x = Xp[k];
                float4 w = *(const float4*)(s_Wa + k*68 + c0);
                a.x += x*w.x; a.y += x*w.y; a.z += x*w.z; a.w += x*w.w;
            }
            a.x += cb[192+c0]; a.y += cb[192+c0+1]; a.z += cb[192+c0+2]; a.w += cb[192+c0+3];
            a.x = 0.2f*a.x + 0.8f*a.x*sigf(a.x);
            a.y = 0.2f*a.y + 0.8f*a.y*sigf(a.y);
            a.z = 0.2f*a.z + 0.8f*a.z*sigf(a.z);
            a.w = 0.2f*a.w + 0.8f*a.w*sigf(a.w);
            float s4 = a.x*cb[256+c0] + a.y*cb[256+c0+1] + a.z*cb[256+c0+2] + a.w*cb[256+c0+3];
            float lg = s4 + __shfl_xor_sync(0xffffffffu, s4, 1);
            if ((tx & 1) == 0){
                int h = tx >> 1;
                g_logit[(size_t)(base+rg)*8 + h] = lg;
                atomicMax(&g_nmax[dst*8 + h], fkey(lg));
            }
        }
    }
}

// ================= K3: value GEMM + weighted scatter (16 edges/iter) ============
// thread tile: 10 rows (9 msg rows + gate-from-row0) x 4 cols, one edge per
// 16-thread group. Postprocess fully in registers; float4 atomic scatter.
__global__ __launch_bounds__(256, 2) void k_edgeB(
    const float* __restrict__ eattr, const int* __restrict__ esrc,
    const int* __restrict__ edst,    const float* __restrict__ Wv,
    const float* __restrict__ bv)
{
    extern __shared__ float sm[];
    float* s_W  = sm;                // [64][128] raw Wv
    float* s_X  = s_W + 64*128;      // [144][68]  (16 edges x 9 rows)
    float* s_wl = s_X + 144*68;      // [16][192]
    float* s_ea = s_wl + 16*192;     // [16][12]
    float* s_sw = s_ea + 192;        // [16][8] softmax numerators
    float* s_bv = s_sw + 128;        // 128
    int tid = threadIdx.x;
    for (int t = tid; t < 8192; t += 256) s_W[t] = Wv[t];
    if (tid < 128) s_bv[tid] = bv[tid];
    __syncthreads();

    int w = tid>>5, lane = tid&31;
    int eA = 2*w, eB = eA+1;
    int rg = tid>>4;                 // edge index 0..15
    int tx = tid&15;
    int c0 = tx*4;

    for (int base = blockIdx.x*16; base < NE; base += gridDim.x*16){
        __syncthreads();
        // -------- per-warp: load metadata + build X rows for edges eA,eB ------
        int srcA = esrc[base+eA], srcB = esrc[base+eB];
        int dstA = edst[base+eA], dstB = edst[base+eB];
        #pragma unroll
        for (int t = lane; t < 96; t += 32){
            int ee = (t >= 48) ? eB : eA;
            int off = (t >= 48) ? (t-48)*4 : t*4;
            float4 v = *(const float4*)(g_wlc + (size_t)(base+ee)*192 + off);
            *(float4*)(s_wl + ee*192 + off) = v;
        }
        if (lane < 18){
            int ee = (lane < 9) ? eA : eB;
            int m  = (lane < 9) ? lane : lane-9;
            s_ea[ee*12 + m] = eattr[(size_t)(base+ee)*9 + m];
        }
        if (lane < 16){
            int ee = eA + (lane>>3);
            int h  = lane&7;
            int d  = (lane < 8) ? dstA : dstB;
            float lg = g_logit[(size_t)(base+ee)*8 + h];
            float mx = fdec(g_nmax[d*8 + h]);
            float ww = __expf(lg - mx);
            s_sw[ee*8 + h] = ww;
            atomicAdd(&g_denom[d*8 + h], ww);
        }
        __syncwarp();
        #pragma unroll
        for (int m = 0; m < 9; m++){
            int l = (m==0) ? 0 : (m<4) ? 1 : 2;
            {
                float2 a = *(const float2*)(g_xs + (size_t)srcA*576 + m*64 + 2*lane);
                float2 b = *(const float2*)(g_xd + (size_t)dstA*576 + m*64 + 2*lane);
                float eam = s_ea[eA*12 + m];
                float2 wl2 = *(const float2*)(s_wl + eA*192 + l*64 + 2*lane);
                float2 v; v.x = (a.x+b.x)*eam*wl2.x; v.y = (a.y+b.y)*eam*wl2.y;
                *(float2*)(s_X + (eA*9+m)*68 + 2*lane) = v;
            }
            {
                float2 a = *(const float2*)(g_xs + (size_t)srcB*576 + m*64 + 2*lane);
                float2 b = *(const float2*)(g_xd + (size_t)dstB*576 + m*64 + 2*lane);
                float eam = s_ea[eB*12 + m];
                float2 wl2 = *(const float2*)(s_wl + eB*192 + l*64 + 2*lane);
                float2 v; v.x = (a.x+b.x)*eam*wl2.x; v.y = (a.y+b.y)*eam*wl2.y;
                *(float2*)(s_X + (eB*9+m)*68 + 2*lane) = v;
            }
        }
        __syncthreads();
        // -------- GEMM: a[0..8] = msg rows @ Wv_value cols c0..c0+3
        //          a[9]   = msg row0 @ Wv_gate cols c0..c0+3
        float4 a[10];
        #pragma unroll
        for (int i = 0; i < 10; i++) a[i] = make_float4(0.f,0.f,0.f,0.f);
        const float* Xp = s_X + rg*9*68;
        #pragma unroll 2
        for (int k = 0; k < 64; k += 2){
            float4 wv0 = *(const float4*)(s_W + k*128 + c0);
            float4 wg0 = *(const float4*)(s_W + k*128 + 64 + c0);
            float4 wv1 = *(const float4*)(s_W + (k+1)*128 + c0);
            float4 wg1 = *(const float4*)(s_W + (k+1)*128 + 64 + c0);
            float2 x0 = *(const float2*)(Xp + k);
            float2 x1 = *(const float2*)(Xp + 68 + k);
            float2 x2 = *(const float2*)(Xp + 136 + k);
            float2 x3 = *(const float2*)(Xp + 204 + k);
            float2 x4 = *(const float2*)(Xp + 272 + k);
            float2 x5 = *(const float2*)(Xp + 340 + k);
            float2 x6 = *(const float2*)(Xp + 408 + k);
            float2 x7 = *(const float2*)(Xp + 476 + k);
            float2 x8 = *(const float2*)(Xp + 544 + k);
            a[0].x += x0.x*wv0.x + x0.y*wv1.x; a[0].y += x0.x*wv0.y + x0.y*wv1.y;
            a[0].z += x0.x*wv0.z + x0.y*wv1.z; a[0].w += x0.x*wv0.w + x0.y*wv1.w;
            a[1].x += x1.x*wv0.x + x1.y*wv1.x; a[1].y += x1.x*wv0.y + x1.y*wv1.y;
            a[1].z += x1.x*wv0.z + x1.y*wv1.z; a[1].w += x1.x*wv0.w + x1.y*wv1.w;
            a[2].x += x2.x*wv0.x + x2.y*wv1.x; a[2].y += x2.x*wv0.y + x2.y*wv1.y;
            a[2].z += x2.x*wv0.z + x2.y*wv1.z; a[2].w += x2.x*wv0.w + x2.y*wv1.w;
            a[3].x += x3.x*wv0.x + x3.y*wv1.x; a[3].y += x3.x*wv0.y + x3.y*wv1.y;
            a[3].z += x3.x*wv0.z + x3.y*wv1.z; a[3].w += x3.x*wv0.w + x3.y*wv1.w;
            a[4].x += x4.x*wv0.x + x4.y*wv1.x; a[4].y += x4.x*wv0.y + x4.y*wv1.y;
            a[4].z += x4.x*wv0.z + x4.y*wv1.z; a[4].w += x4.x*wv0.w + x4.y*wv1.w;
            a[5].x += x5.x*wv0.x + x5.y*wv1.x; a[5].y += x5.x*wv0.y + x5.y*wv1.y;
            a[5].z += x5.x*wv0.z + x5.y*wv1.z; a[5].w += x5.x*wv0.w + x5.y*wv1.w;
            a[6].x += x6.x*wv0.x + x6.y*wv1.x; a[6].y += x6.x*wv0.y + x6.y*wv1.y;
            a[6].z += x6.x*wv0.z + x6.y*wv1.z; a[6].w += x6.x*wv0.w + x6.y*wv1.w;
            a[7].x += x7.x*wv0.x + x7.y*wv1.x; a[7].y += x7.x*wv0.y + x7.y*wv1.y;
            a[7].z += x7.x*wv0.z + x7.y*wv1.z; a[7].w += x7.x*wv0.w + x7.y*wv1.w;
            a[8].x += x8.x*wv0.x + x8.y*wv1.x; a[8].y += x8.x*wv0.y + x8.y*wv1.y;
            a[8].z += x8.x*wv0.z + x8.y*wv1.z; a[8].w += x8.x*wv0.w + x8.y*wv1.w;
            a[9].x += x0.x*wg0.x + x0.y*wg1.x; a[9].y += x0.x*wg0.y + x0.y*wg1.y;
            a[9].z += x0.x*wg0.z + x0.y*wg1.z; a[9].w += x0.x*wg0.w + x0.y*wg1.w;
        }
        // biases
        a[0].x += s_bv[c0];    a[0].y += s_bv[c0+1];    a[0].z += s_bv[c0+2];    a[0].w += s_bv[c0+3];
        a[9].x += s_bv[64+c0]; a[9].y += s_bv[64+c0+1]; a[9].z += s_bv[64+c0+2]; a[9].w += s_bv[64+c0+3];
        // -------- postprocess + scatter (all in registers) --------------------
        {
            int d = edst[base + rg];
            float gx = sigf(a[9].x), gy = sigf(a[9].y), gz = sigf(a[9].z), gw = sigf(a[9].w);
            float wh = s_sw[rg*8 + (c0>>3)];
            float4* accp = (float4*)(g_acc + (size_t)d*576 + c0);
            #pragma unroll
            for (int m = 0; m < 9; m++){
                int l = (m==0) ? 0 : (m<4) ? 1 : 2;
                float4 wl4 = *(const float4*)(s_wl + rg*192 + l*64 + c0);
                float cm = s_ea[rg*12 + m] * wh;
                float4 y = a[m];
                float4 o;
                if (m == 0){
                    o.x = y.x*sigf(y.x); o.y = y.y*sigf(y.y);
                    o.z = y.z*sigf(y.z); o.w = y.w*sigf(y.w);
                } else {
                    o.x = y.x*gx; o.y = y.y*gy; o.z = y.z*gz; o.w = y.w*gw;
                }
                o.x *= cm*wl4.x; o.y *= cm*wl4.y; o.z *= cm*wl4.z; o.w *= cm*wl4.w;
                atomicAdd(accp + m*16, o);
            }
        }
    }
}

// ================= K4: normalize + projection (8 nodes/iter) ====================
__global__ __launch_bounds__(256) void k_out(
    const float* __restrict__ Wp, const float* __restrict__ bp, float* __restrict__ out)
{
    extern __shared__ float sm[];
    float* s_W  = sm;              // [64][68]
    float* s_X  = s_W + 64*68;     // [80][68]
    float* s_b  = s_X + 80*68;     // 64
    float* s_inv= s_b + 64;        // 64
    int tid = threadIdx.x;
    for (int t = tid; t < 4096; t += 256){
        int k = t>>6, j = t&63;
        s_W[k*68 + j] = Wp[t];
    }
    if (tid < 64) s_b[tid] = bp[tid];
    for (int t = tid; t < 8*68; t += 256) s_X[72*68 + t] = 0.f;
    __syncthreads();

    int rg = tid>>4, tx = tid&15, c0 = tx*4, r0 = rg*5;

    for (int base = blockIdx.x*8; base < NN; base += gridDim.x*8){
        __syncthreads();
        if (tid < 64){
            int e = tid>>3, h = tid&7;
            s_inv[tid] = 1.f/(g_denom[(base+e)*8 + h] + 1e-16f);
        }
        __syncthreads();
        for (int i = tid; i < 8*576; i += 256){
            int n = i/576, rem = i - n*576;
            int row = n*9 + (rem>>6), col = rem&63;
            s_X[row*68 + col] = g_acc[(size_t)(base+n)*576 + rem] * s_inv[n*8 + (col>>3)];
        }
        __syncthreads();
        float4 a0 = {0,0,0,0}, a1 = a0, a2 = a0, a3 = a0, a4 = a0;
        const float* Xp = s_X + r0*68;
        #pragma unroll 8
        for (int k = 0; k < 64; k++){
            float4 w = *(const float4*)(s_W + k*68 + c0);
            float x0 = Xp[k], x1 = Xp[68+k], x2 = Xp[136+k], x3 = Xp[204+k], x4 = Xp[272+k];
            a0.x += x0*w.x; a0.y += x0*w.y; a0.z += x0*w.z; a0.w += x0*w.w;
            a1.x += x1*w.x; a1.y += x1*w.y; a1.z += x1*w.z; a1.w += x1*w.w;
            a2.x += x2*w.x; a2.y += x2*w.y; a2.z += x2*w.z; a2.w += x2*w.w;
            a3.x += x3*w.x; a3.y += x3*w.y; a3.z += x3*w.z; a3.w += x3*w.w;
            a4.x += x4*w.x; a4.y += x4*w.y; a4.z += x4*w.z; a4.w += x4*w.w;
        }
        float4 acc[5] = {a0,a1,a2,a3,a4};
        #pragma unroll
        for (int i = 0; i < 5; i++){
            int r = r0 + i;
            if (r < 72){
                int n = base + r/9, m = r%9;
                float4 v = acc[i];
                if (m == 0){
                    v.x += s_b[c0]; v.y += s_b[c0+1]; v.z += s_b[c0+2]; v.w += s_b[c0+3];
                }
                *(float4*)(out + (size_t)n*576 + m*64 + c0) = v;
            }
        }
    }
}

extern "C" void kernel_launch(void* const* d_in, const int* in_sizes, int n_in,
                              void* d_out, int out_size)
{
    const float* node_input = (const float*)d_in[0];
    const float* edge_attr  = (const float*)d_in[1];
    const float* edge_scal  = (const float*)d_in[2];
    const float* W_src = (const float*)d_in[3];
    const float* b_src = (const float*)d_in[4];
    const float* W_dst = (const float*)d_in[5];
    const float* rW1   = (const float*)d_in[6];
    const float* rb1   = (const float*)d_in[7];
    const float* lng   = (const float*)d_in[8];
    const float* lnb   = (const float*)d_in[9];
    const float* rW2   = (const float*)d_in[10];
    const float* roff  = (const float*)d_in[11];
    const float* Wa    = (const float*)d_in[12];
    const float* ba    = (const float*)d_in[13];
    const float* adot  = (const float*)d_in[14];
    const float* Wv    = (const float*)d_in[15];
    const float* bv    = (const float*)d_in[16];
    const float* Wp    = (const float*)d_in[17];
    const float* bp    = (const float*)d_in[18];
    const int*   esrc  = (const int*)d_in[19];
    const int*   edst  = (const int*)d_in[20];
    float* out = (float*)d_out;

    const int smem_node = (64*128 + 40*68 + 64) * 4;
    const int smem_eA   = (64*68*2 + 64*192 + 512 + 16*68*3 + 16*192) * 4;
    const int smem_eB   = (64*128 + 144*68 + 16*192 + 192 + 128 + 128) * 4;
    const int smem_out  = (64*68 + 80*68 + 64 + 64) * 4;

    cudaFuncSetAttribute(k_node,  cudaFuncAttributeMaxDynamicSharedMemorySize, smem_node);
    cudaFuncSetAttribute(k_edgeA, cudaFuncAttributeMaxDynamicSharedMemorySize, smem_eA);
    cudaFuncSetAttribute(k_edgeB, cudaFuncAttributeMaxDynamicSharedMemorySize, smem_eB);
    cudaFuncSetAttribute(k_out,   cudaFuncAttributeMaxDynamicSharedMemorySize, smem_out);

    k_init<<<2048, 256>>>();
    k_node<<<296, 256, smem_node>>>(node_input, W_src, b_src, W_dst);
    k_edgeA<<<296, 256, smem_eA>>>(edge_scal, edge_attr, esrc, edst,
                                   rW1, rb1, lng, lnb, rW2, roff, Wa, ba, adot);
    k_edgeB<<<296, 256, smem_eB>>>(edge_attr, esrc, edst, Wv, bv);
    k_out<<<296, 256, smem_out>>>(Wp, bp, out);
}

// round 4
// speedup vs baseline: 1.9533x; 1.0353x over previous
#include <cuda_runtime.h>
#include <math.h>

#define NN 10000
#define NE 160000
#define MM 9
#define CC 64
#define HH 8

// ---------------- scratch (static device globals; no allocation) ----------------
__device__ float    g_xs[NN*MM*CC];        // node src-linear   (23 MB)
__device__ float    g_xd[NN*MM*CC];        // node dst-linear   (23 MB)
__device__ float    g_wlc[(size_t)NE*192]; // radial weights    (123 MB)
__device__ float    g_logit[NE*HH];
__device__ unsigned g_nmax[NN*HH];         // monotone-mapped float max
__device__ float    g_denom[NN*HH];
__device__ float    g_acc[NN*MM*CC];

__device__ __forceinline__ unsigned fkey(float f){
    int i = __float_as_int(f);
    return (i >= 0) ? ((unsigned)i ^ 0x80000000u) : ~(unsigned)i;
}
__device__ __forceinline__ float fdec(unsigned u){
    int i = (u & 0x80000000u) ? (int)(u ^ 0x80000000u) : (int)(~u);
    return __int_as_float(i);
}
__device__ __forceinline__ float sigf(float x){ return 1.f/(1.f + __expf(-x)); }

__global__ void k_init(){
    int i = blockIdx.x*blockDim.x + threadIdx.x;
    int st = gridDim.x*blockDim.x;
    for (int t = i; t < NN*MM*CC; t += st) g_acc[t] = 0.f;
    for (int t = i; t < NN*HH;    t += st){ g_denom[t] = 0.f; g_nmax[t] = fkey(-INFINITY); }
}

// ================= K1: node linear (GEMM: 4 nodes -> X[40x64] @ W[64x128]) =====
__global__ __launch_bounds__(256) void k_node(
    const float* __restrict__ xin, const float* __restrict__ Ws,
    const float* __restrict__ bs,  const float* __restrict__ Wd)
{
    extern __shared__ float sm[];
    float* s_W = sm;               // [64][128]  col 0-63: Ws, 64-127: Wd
    float* s_X = s_W + 64*128;     // [40][68]
    float* s_b = s_X + 40*68;      // 64
    int tid = threadIdx.x;
    for (int t = tid; t < 8192; t += 256){
        int k = t>>7, c = t&127;
        s_W[t] = (c < 64) ? Ws[k*64 + c] : Wd[k*64 + (c-64)];
    }
    if (tid < 64) s_b[tid] = bs[tid];
    for (int t = tid; t < 4*68; t += 256) s_X[36*68 + t] = 0.f;
    __syncthreads();

    int rg = tid>>5;              // 0..7  -> rows rg*5..rg*5+4
    int c0 = (tid&31)*4;          // 0..124
    int r0 = rg*5;

    for (int base = blockIdx.x*4; base < NN; base += gridDim.x*4){
        __syncthreads();
        for (int i = tid; i < 4*576; i += 256){
            int n = i/576, rem = i - n*576;
            int row = n*9 + (rem>>6), col = rem&63;
            s_X[row*68 + col] = xin[(size_t)(base+n)*576 + rem];
        }
        __syncthreads();
        float4 a0 = {0,0,0,0}, a1 = a0, a2 = a0, a3 = a0, a4 = a0;
        const float* Xp = s_X + r0*68;
        #pragma unroll 4
        for (int k = 0; k < 64; k += 4){
            float4 w0 = *(const float4*)(s_W + (k  )*128 + c0);
            float4 w1 = *(const float4*)(s_W + (k+1)*128 + c0);
            float4 w2 = *(const float4*)(s_W + (k+2)*128 + c0);
            float4 w3 = *(const float4*)(s_W + (k+3)*128 + c0);
            float4 x0 = *(const float4*)(Xp + k);
            float4 x1 = *(const float4*)(Xp + 68 + k);
            float4 x2 = *(const float4*)(Xp + 136 + k);
            float4 x3 = *(const float4*)(Xp + 204 + k);
            float4 x4 = *(const float4*)(Xp + 272 + k);
            a0.x += x0.x*w0.x + x0.y*w1.x + x0.z*w2.x + x0.w*w3.x;
            a0.y += x0.x*w0.y + x0.y*w1.y + x0.z*w2.y + x0.w*w3.y;
            a0.z += x0.x*w0.z + x0.y*w1.z + x0.z*w2.z + x0.w*w3.z;
            a0.w += x0.x*w0.w + x0.y*w1.w + x0.z*w2.w + x0.w*w3.w;
            a1.x += x1.x*w0.x + x1.y*w1.x + x1.z*w2.x + x1.w*w3.x;
            a1.y += x1.x*w0.y + x1.y*w1.y + x1.z*w2.y + x1.w*w3.y;
            a1.z += x1.x*w0.z + x1.y*w1.z + x1.z*w2.z + x1.w*w3.z;
            a1.w += x1.x*w0.w + x1.y*w1.w + x1.z*w2.w + x1.w*w3.w;
            a2.x += x2.x*w0.x + x2.y*w1.x + x2.z*w2.x + x2.w*w3.x;
            a2.y += x2.x*w0.y + x2.y*w1.y + x2.z*w2.y + x2.w*w3.y;
            a2.z += x2.x*w0.z + x2.y*w1.z + x2.z*w2.z + x2.w*w3.z;
            a2.w += x2.x*w0.w + x2.y*w1.w + x2.z*w2.w + x2.w*w3.w;
            a3.x += x3.x*w0.x + x3.y*w1.x + x3.z*w2.x + x3.w*w3.x;
            a3.y += x3.x*w0.y + x3.y*w1.y + x3.z*w2.y + x3.w*w3.y;
            a3.z += x3.x*w0.z + x3.y*w1.z + x3.z*w2.z + x3.w*w3.z;
            a3.w += x3.x*w0.w + x3.y*w1.w + x3.z*w2.w + x3.w*w3.w;
            a4.x += x4.x*w0.x + x4.y*w1.x + x4.z*w2.x + x4.w*w3.x;
            a4.y += x4.x*w0.y + x4.y*w1.y + x4.z*w2.y + x4.w*w3.y;
            a4.z += x4.x*w0.z + x4.y*w1.z + x4.z*w2.z + x4.w*w3.z;
            a4.w += x4.x*w0.w + x4.y*w1.w + x4.z*w2.w + x4.w*w3.w;
        }
        float4 acc[5] = {a0,a1,a2,a3,a4};
        #pragma unroll
        for (int i = 0; i < 5; i++){
            int r = r0 + i;
            if (r < 36){
                int n = base + r/9, m = r%9;
                float4 v = acc[i];
                if (m == 0 && c0 < 64){
                    v.x += s_b[c0]; v.y += s_b[c0+1]; v.z += s_b[c0+2]; v.w += s_b[c0+3];
                }
                if (c0 < 64) *(float4*)(g_xs + (size_t)n*576 + m*64 + c0) = v;
                else         *(float4*)(g_xd + (size_t)n*576 + m*64 + (c0-64)) = v;
            }
        }
    }
}

// ================= K2: radial MLP + alpha logits (16 edges/iter) ================
__global__ __launch_bounds__(256) void k_edgeA(
    const float* __restrict__ esc, const float* __restrict__ eattr,
    const int* __restrict__ esrc,  const int* __restrict__ edst,
    const float* __restrict__ W1,  const float* __restrict__ b1,
    const float* __restrict__ lng, const float* __restrict__ lnb,
    const float* __restrict__ W2,  const float* __restrict__ off,
    const float* __restrict__ Wa,  const float* __restrict__ ba,
    const float* __restrict__ adot)
{
    extern __shared__ float sm[];
    float* s_W1 = sm;               // [64][68]
    float* s_Wa = s_W1 + 64*68;     // [64][68]
    float* s_W2 = s_Wa + 64*68;     // [64][192] raw
    float* cb   = s_W2 + 64*192;    // b1|lng|lnb|ba|adot|off  = 512
    float* s_S  = cb + 512;         // [16][68]
    float* s_H  = s_S + 16*68;      // [16][68]
    float* s_M0 = s_H + 16*68;      // [16][68]
    float* s_WL = s_M0 + 16*68;     // [16][192]
    int tid = threadIdx.x;
    for (int t = tid; t < 4096; t += 256){
        int k = t>>6, j = t&63;
        s_W1[k*68+j] = W1[t]; s_Wa[k*68+j] = Wa[t];
    }
    for (int t = tid; t < 12288; t += 256) s_W2[t] = W2[t];
    if (tid < 64){
        cb[tid] = b1[tid]; cb[64+tid] = lng[tid]; cb[128+tid] = lnb[tid];
        cb[192+tid] = ba[tid]; cb[256+tid] = adot[tid];
    }
    for (int t = tid; t < 192; t += 256) cb[320+t] = off[t];
    __syncthreads();

    int rg = tid>>4;            // 0..15 (edge row)
    int tx = tid&15;
    int c0 = tx*4;

    for (int base = blockIdx.x*16; base < NE; base += gridDim.x*16){
        __syncthreads();
        for (int i = tid; i < 16*64; i += 256){
            int e = i>>6, c = i&63;
            s_S[e*68 + c] = esc[(size_t)(base+e)*64 + c];
        }
        __syncthreads();
        // GEMM1: H = S @ W1   (k vectorized by 4)
        {
            float4 a = {0,0,0,0};
            const float* Xp = s_S + rg*68;
            #pragma unroll 4
            for (int k = 0; k < 64; k += 4){
                float4 x = *(const float4*)(Xp + k);
                float4 w0 = *(const float4*)(s_W1 + (k  )*68 + c0);
                float4 w1 = *(const float4*)(s_W1 + (k+1)*68 + c0);
                float4 w2 = *(const float4*)(s_W1 + (k+2)*68 + c0);
                float4 w3 = *(const float4*)(s_W1 + (k+3)*68 + c0);
                a.x += x.x*w0.x + x.y*w1.x + x.z*w2.x + x.w*w3.x;
                a.y += x.x*w0.y + x.y*w1.y + x.z*w2.y + x.w*w3.y;
                a.z += x.x*w0.z + x.y*w1.z + x.z*w2.z + x.w*w3.z;
                a.w += x.x*w0.w + x.y*w1.w + x.z*w2.w + x.w*w3.w;
            }
            a.x += cb[c0]; a.y += cb[c0+1]; a.z += cb[c0+2]; a.w += cb[c0+3];
            float s = a.x+a.y+a.z+a.w;
            float q = a.x*a.x+a.y*a.y+a.z*a.z+a.w*a.w;
            #pragma unroll
            for (int o = 8; o > 0; o >>= 1){
                s += __shfl_xor_sync(0xffffffffu, s, o);
                q += __shfl_xor_sync(0xffffffffu, q, o);
            }
            float mu = s*(1.f/64.f);
            float var = q*(1.f/64.f) - mu*mu;
            float rs = rsqrtf(var + 1e-5f);
            float4 h;
            h.x = (a.x-mu)*rs*cb[64+c0  ] + cb[128+c0  ];
            h.y = (a.y-mu)*rs*cb[64+c0+1] + cb[128+c0+1];
            h.z = (a.z-mu)*rs*cb[64+c0+2] + cb[128+c0+2];
            h.w = (a.w-mu)*rs*cb[64+c0+3] + cb[128+c0+3];
            h.x *= sigf(h.x); h.y *= sigf(h.y); h.z *= sigf(h.z); h.w *= sigf(h.w);
            *(float4*)(s_H + rg*68 + c0) = h;
        }
        __syncthreads();
        // GEMM2: WL = H @ W2   (k vectorized by 4 on x)
        {
            int rgr = tid>>6;
            int cc  = tid&63;
            float acc[4][3] = {{0,0,0},{0,0,0},{0,0,0},{0,0,0}};
            #pragma unroll 2
            for (int k = 0; k < 64; k += 4){
                float4 x0 = *(const float4*)(s_H + (rgr   )*68 + k);
                float4 x1 = *(const float4*)(s_H + (rgr+4 )*68 + k);
                float4 x2 = *(const float4*)(s_H + (rgr+8 )*68 + k);
                float4 x3 = *(const float4*)(s_H + (rgr+12)*68 + k);
                {
                    float w0 = s_W2[(k  )*192 + cc], w1 = s_W2[(k  )*192 + cc + 64], w2 = s_W2[(k  )*192 + cc + 128];
                    acc[0][0]+=x0.x*w0; acc[0][1]+=x0.x*w1; acc[0][2]+=x0.x*w2;
                    acc[1][0]+=x1.x*w0; acc[1][1]+=x1.x*w1; acc[1][2]+=x1.x*w2;
                    acc[2][0]+=x2.x*w0; acc[2][1]+=x2.x*w1; acc[2][2]+=x2.x*w2;
                    acc[3][0]+=x3.x*w0; acc[3][1]+=x3.x*w1; acc[3][2]+=x3.x*w2;
                }
                {
                    float w0 = s_W2[(k+1)*192 + cc], w1 = s_W2[(k+1)*192 + cc + 64], w2 = s_W2[(k+1)*192 + cc + 128];
                    acc[0][0]+=x0.y*w0; acc[0][1]+=x0.y*w1; acc[0][2]+=x0.y*w2;
                    acc[1][0]+=x1.y*w0; acc[1][1]+=x1.y*w1; acc[1][2]+=x1.y*w2;
                    acc[2][0]+=x2.y*w0; acc[2][1]+=x2.y*w1; acc[2][2]+=x2.y*w2;
                    acc[3][0]+=x3.y*w0; acc[3][1]+=x3.y*w1; acc[3][2]+=x3.y*w2;
                }
                {
                    float w0 = s_W2[(k+2)*192 + cc], w1 = s_W2[(k+2)*192 + cc + 64], w2 = s_W2[(k+2)*192 + cc + 128];
                    acc[0][0]+=x0.z*w0; acc[0][1]+=x0.z*w1; acc[0][2]+=x0.z*w2;
                    acc[1][0]+=x1.z*w0; acc[1][1]+=x1.z*w1; acc[1][2]+=x1.z*w2;
                    acc[2][0]+=x2.z*w0; acc[2][1]+=x2.z*w1; acc[2][2]+=x2.z*w2;
                    acc[3][0]+=x3.z*w0; acc[3][1]+=x3.z*w1; acc[3][2]+=x3.z*w2;
                }
                {
                    float w0 = s_W2[(k+3)*192 + cc], w1 = s_W2[(k+3)*192 + cc + 64], w2 = s_W2[(k+3)*192 + cc + 128];
                    acc[0][0]+=x0.w*w0; acc[0][1]+=x0.w*w1; acc[0][2]+=x0.w*w2;
                    acc[1][0]+=x1.w*w0; acc[1][1]+=x1.w*w1; acc[1][2]+=x1.w*w2;
                    acc[2][0]+=x2.w*w0; acc[2][1]+=x2.w*w1; acc[2][2]+=x2.w*w2;
                    acc[3][0]+=x3.w*w0; acc[3][1]+=x3.w*w1; acc[3][2]+=x3.w*w2;
                }
            }
            #pragma unroll
            for (int i = 0; i < 4; i++){
                int r = rgr + i*4;
                #pragma unroll
                for (int j = 0; j < 3; j++){
                    float v = acc[i][j] + cb[320 + cc + 64*j];
                    s_WL[r*192 + cc + 64*j] = v;
                    g_wlc[(size_t)(base+r)*192 + cc + 64*j] = v;
                }
            }
        }
        __syncthreads();
        // M0 build
        int dst;
        {
            int e = rg;
            int src = esrc[base+e]; dst = edst[base+e];
            float ea0 = eattr[(size_t)(base+e)*9];
            float4 xs = *(const float4*)(g_xs + (size_t)src*576 + c0);
            float4 xd = *(const float4*)(g_xd + (size_t)dst*576 + c0);
            float4 wl = *(const float4*)(s_WL + e*192 + c0);
            float4 m0;
            m0.x = (xs.x+xd.x)*ea0*wl.x; m0.y = (xs.y+xd.y)*ea0*wl.y;
            m0.z = (xs.z+xd.z)*ea0*wl.z; m0.w = (xs.w+xd.w)*ea0*wl.w;
            *(float4*)(s_M0 + e*68 + c0) = m0;
        }
        __syncthreads();
        // GEMM3: alpha logits   (k vectorized by 4)
        {
            float4 a = {0,0,0,0};
            const float* Xp = s_M0 + rg*68;
            #pragma unroll 4
            for (int k = 0; k < 64; k += 4){
                float4 x = *(const float4*)(Xp + k);
                float4 w0 = *(const float4*)(s_Wa + (k  )*68 + c0);
                float4 w1 = *(const float4*)(s_Wa + (k+1)*68 + c0);
                float4 w2 = *(const float4*)(s_Wa + (k+2)*68 + c0);
                float4 w3 = *(const float4*)(s_Wa + (k+3)*68 + c0);
                a.x += x.x*w0.x + x.y*w1.x + x.z*w2.x + x.w*w3.x;
                a.y += x.x*w0.y + x.y*w1.y + x.z*w2.y + x.w*w3.y;
                a.z += x.x*w0.z + x.y*w1.z + x.z*w2.z + x.w*w3.z;
                a.w += x.x*w0.w + x.y*w1.w + x.z*w2.w + x.w*w3.w;
            }
            a.x += cb[192+c0]; a.y += cb[192+c0+1]; a.z += cb[192+c0+2]; a.w += cb[192+c0+3];
            a.x = 0.2f*a.x + 0.8f*a.x*sigf(a.x);
            a.y = 0.2f*a.y + 0.8f*a.y*sigf(a.y);
            a.z = 0.2f*a.z + 0.8f*a.z*sigf(a.z);
            a.w = 0.2f*a.w + 0.8f*a.w*sigf(a.w);
            float s4 = a.x*cb[256+c0] + a.y*cb[256+c0+1] + a.z*cb[256+c0+2] + a.w*cb[256+c0+3];
            float lg = s4 + __shfl_xor_sync(0xffffffffu, s4, 1);
            if ((tx & 1) == 0){
                int h = tx >> 1;
                g_logit[(size_t)(base+rg)*8 + h] = lg;
                atomicMax(&g_nmax[dst*8 + h], fkey(lg));
            }
        }
    }
}

// ================= K3: value GEMM + weighted scatter (16 edges/iter) ============
__global__ __launch_bounds__(256, 2) void k_edgeB(
    const float* __restrict__ eattr, const int* __restrict__ esrc,
    const int* __restrict__ edst,    const float* __restrict__ Wv,
    const float* __restrict__ bv)
{
    extern __shared__ float sm[];
    float* s_W  = sm;                // [64][128] raw Wv
    float* s_X  = s_W + 64*128;      // [144][68]  (16 edges x 9 rows)
    float* s_wl = s_X + 144*68;      // [16][192]
    float* s_ea = s_wl + 16*192;     // [16][12]
    float* s_sw = s_ea + 192;        // [16][8] softmax numerators
    float* s_bv = s_sw + 128;        // 128
    int tid = threadIdx.x;
    for (int t = tid; t < 8192; t += 256) s_W[t] = Wv[t];
    if (tid < 128) s_bv[tid] = bv[tid];
    __syncthreads();

    int w = tid>>5, lane = tid&31;
    int eA = 2*w, eB = eA+1;
    int rg = tid>>4;                 // edge index 0..15
    int tx = tid&15;
    int c0 = tx*4;

    for (int base = blockIdx.x*16; base < NE; base += gridDim.x*16){
        __syncthreads();
        int srcA = esrc[base+eA], srcB = esrc[base+eB];
        int dstA = edst[base+eA], dstB = edst[base+eB];
        #pragma unroll
        for (int t = lane; t < 96; t += 32){
            int ee = (t >= 48) ? eB : eA;
            int off = (t >= 48) ? (t-48)*4 : t*4;
            float4 v = *(const float4*)(g_wlc + (size_t)(base+ee)*192 + off);
            *(float4*)(s_wl + ee*192 + off) = v;
        }
        if (lane < 18){
            int ee = (lane < 9) ? eA : eB;
            int m  = (lane < 9) ? lane : lane-9;
            s_ea[ee*12 + m] = eattr[(size_t)(base+ee)*9 + m];
        }
        if (lane < 16){
            int ee = eA + (lane>>3);
            int h  = lane&7;
            int d  = (lane < 8) ? dstA : dstB;
            float lg = g_logit[(size_t)(base+ee)*8 + h];
            float mx = fdec(g_nmax[d*8 + h]);
            float ww = __expf(lg - mx);
            s_sw[ee*8 + h] = ww;
            atomicAdd(&g_denom[d*8 + h], ww);
        }
        __syncwarp();
        #pragma unroll
        for (int m = 0; m < 9; m++){
            int l = (m==0) ? 0 : (m<4) ? 1 : 2;
            {
                float2 a = *(const float2*)(g_xs + (size_t)srcA*576 + m*64 + 2*lane);
                float2 b = *(const float2*)(g_xd + (size_t)dstA*576 + m*64 + 2*lane);
                float eam = s_ea[eA*12 + m];
                float2 wl2 = *(const float2*)(s_wl + eA*192 + l*64 + 2*lane);
                float2 v; v.x = (a.x+b.x)*eam*wl2.x; v.y = (a.y+b.y)*eam*wl2.y;
                *(float2*)(s_X + (eA*9+m)*68 + 2*lane) = v;
            }
            {
                float2 a = *(const float2*)(g_xs + (size_t)srcB*576 + m*64 + 2*lane);
                float2 b = *(const float2*)(g_xd + (size_t)dstB*576 + m*64 + 2*lane);
                float eam = s_ea[eB*12 + m];
                float2 wl2 = *(const float2*)(s_wl + eB*192 + l*64 + 2*lane);
                float2 v; v.x = (a.x+b.x)*eam*wl2.x; v.y = (a.y+b.y)*eam*wl2.y;
                *(float2*)(s_X + (eB*9+m)*68 + 2*lane) = v;
            }
        }
        __syncthreads();
        float4 a[10];
        #pragma unroll
        for (int i = 0; i < 10; i++) a[i] = make_float4(0.f,0.f,0.f,0.f);
        const float* Xp = s_X + rg*9*68;
        #pragma unroll 2
        for (int k = 0; k < 64; k += 2){
            float4 wv0 = *(const float4*)(s_W + k*128 + c0);
            float4 wg0 = *(const float4*)(s_W + k*128 + 64 + c0);
            float4 wv1 = *(const float4*)(s_W + (k+1)*128 + c0);
            float4 wg1 = *(const float4*)(s_W + (k+1)*128 + 64 + c0);
            float2 x0 = *(const float2*)(Xp + k);
            float2 x1 = *(const float2*)(Xp + 68 + k);
            float2 x2 = *(const float2*)(Xp + 136 + k);
            float2 x3 = *(const float2*)(Xp + 204 + k);
            float2 x4 = *(const float2*)(Xp + 272 + k);
            float2 x5 = *(const float2*)(Xp + 340 + k);
            float2 x6 = *(const float2*)(Xp + 408 + k);
            float2 x7 = *(const float2*)(Xp + 476 + k);
            float2 x8 = *(const float2*)(Xp + 544 + k);
            a[0].x += x0.x*wv0.x + x0.y*wv1.x; a[0].y += x0.x*wv0.y + x0.y*wv1.y;
            a[0].z += x0.x*wv0.z + x0.y*wv1.z; a[0].w += x0.x*wv0.w + x0.y*wv1.w;
            a[1].x += x1.x*wv0.x + x1.y*wv1.x; a[1].y += x1.x*wv0.y + x1.y*wv1.y;
            a[1].z += x1.x*wv0.z + x1.y*wv1.z; a[1].w += x1.x*wv0.w + x1.y*wv1.w;
            a[2].x += x2.x*wv0.x + x2.y*wv1.x; a[2].y += x2.x*wv0.y + x2.y*wv1.y;
            a[2].z += x2.x*wv0.z + x2.y*wv1.z; a[2].w += x2.x*wv0.w + x2.y*wv1.w;
            a[3].x += x3.x*wv0.x + x3.y*wv1.x; a[3].y += x3.x*wv0.y + x3.y*wv1.y;
            a[3].z += x3.x*wv0.z + x3.y*wv1.z; a[3].w += x3.x*wv0.w + x3.y*wv1.w;
            a[4].x += x4.x*wv0.x + x4.y*wv1.x; a[4].y += x4.x*wv0.y + x4.y*wv1.y;
            a[4].z += x4.x*wv0.z + x4.y*wv1.z; a[4].w += x4.x*wv0.w + x4.y*wv1.w;
            a[5].x += x5.x*wv0.x + x5.y*wv1.x; a[5].y += x5.x*wv0.y + x5.y*wv1.y;
            a[5].z += x5.x*wv0.z + x5.y*wv1.z; a[5].w += x5.x*wv0.w + x5.y*wv1.w;
            a[6].x += x6.x*wv0.x + x6.y*wv1.x; a[6].y += x6.x*wv0.y + x6.y*wv1.y;
            a[6].z += x6.x*wv0.z + x6.y*wv1.z; a[6].w += x6.x*wv0.w + x6.y*wv1.w;
            a[7].x += x7.x*wv0.x + x7.y*wv1.x; a[7].y += x7.x*wv0.y + x7.y*wv1.y;
            a[7].z += x7.x*wv0.z + x7.y*wv1.z; a[7].w += x7.x*wv0.w + x7.y*wv1.w;
            a[8].x += x8.x*wv0.x + x8.y*wv1.x; a[8].y += x8.x*wv0.y + x8.y*wv1.y;
            a[8].z += x8.x*wv0.z + x8.y*wv1.z; a[8].w += x8.x*wv0.w + x8.y*wv1.w;
            a[9].x += x0.x*wg0.x + x0.y*wg1.x; a[9].y += x0.x*wg0.y + x0.y*wg1.y;
            a[9].z += x0.x*wg0.z + x0.y*wg1.z; a[9].w += x0.x*wg0.w + x0.y*wg1.w;
        }
        a[0].x += s_bv[c0];    a[0].y += s_bv[c0+1];    a[0].z += s_bv[c0+2];    a[0].w += s_bv[c0+3];
        a[9].x += s_bv[64+c0]; a[9].y += s_bv[64+c0+1]; a[9].z += s_bv[64+c0+2]; a[9].w += s_bv[64+c0+3];
        {
            int d = edst[base + rg];
            float gx = sigf(a[9].x), gy = sigf(a[9].y), gz = sigf(a[9].z), gw = sigf(a[9].w);
            float wh = s_sw[rg*8 + (c0>>3)];
            float4* accp = (float4*)(g_acc + (size_t)d*576 + c0);
            #pragma unroll
            for (int m = 0; m < 9; m++){
                int l = (m==0) ? 0 : (m<4) ? 1 : 2;
                float4 wl4 = *(const float4*)(s_wl + rg*192 + l*64 + c0);
                float cm = s_ea[rg*12 + m] * wh;
                float4 y = a[m];
                float4 o;
                if (m == 0){
                    o.x = y.x*sigf(y.x); o.y = y.y*sigf(y.y);
                    o.z = y.z*sigf(y.z); o.w = y.w*sigf(y.w);
                } else {
                    o.x = y.x*gx; o.y = y.y*gy; o.z = y.z*gz; o.w = y.w*gw;
                }
                o.x *= cm*wl4.x; o.y *= cm*wl4.y; o.z *= cm*wl4.z; o.w *= cm*wl4.w;
                atomicAdd(accp + m*16, o);
            }
        }
    }
}

// ================= K4: normalize + projection (8 nodes/iter) ====================
__global__ __launch_bounds__(256) void k_out(
    const float* __restrict__ Wp, const float* __restrict__ bp, float* __restrict__ out)
{
    extern __shared__ float sm[];
    float* s_W  = sm;              // [64][68]
    float* s_X  = s_W + 64*68;     // [80][68]
    float* s_b  = s_X + 80*68;     // 64
    float* s_inv= s_b + 64;        // 64
    int tid = threadIdx.x;
    for (int t = tid; t < 4096; t += 256){
        int k = t>>6, j = t&63;
        s_W[k*68 + j] = Wp[t];
    }
    if (tid < 64) s_b[tid] = bp[tid];
    for (int t = tid; t < 8*68; t += 256) s_X[72*68 + t] = 0.f;
    __syncthreads();

    int rg = tid>>4, tx = tid&15, c0 = tx*4, r0 = rg*5;

    for (int base = blockIdx.x*8; base < NN; base += gridDim.x*8){
        __syncthreads();
        if (tid < 64){
            int e = tid>>3, h = tid&7;
            s_inv[tid] = 1.f/(g_denom[(base+e)*8 + h] + 1e-16f);
        }
        __syncthreads();
        for (int i = tid; i < 8*576; i += 256){
            int n = i/576, rem = i - n*576;
            int row = n*9 + (rem>>6), col = rem&63;
            s_X[row*68 + col] = g_acc[(size_t)(base+n)*576 + rem] * s_inv[n*8 + (col>>3)];
        }
        __syncthreads();
        float4 a0 = {0,0,0,0}, a1 = a0, a2 = a0, a3 = a0, a4 = a0;
        const float* Xp = s_X + r0*68;
        #pragma unroll 4
        for (int k = 0; k < 64; k += 4){
            float4 w0 = *(const float4*)(s_W + (k  )*68 + c0);
            float4 w1 = *(const float4*)(s_W + (k+1)*68 + c0);
            float4 w2 = *(const float4*)(s_W + (k+2)*68 + c0);
            float4 w3 = *(const float4*)(s_W + (k+3)*68 + c0);
            float4 x0 = *(const float4*)(Xp + k);
            float4 x1 = *(const float4*)(Xp + 68 + k);
            float4 x2 = *(const float4*)(Xp + 136 + k);
            float4 x3 = *(const float4*)(Xp + 204 + k);
            float4 x4 = *(const float4*)(Xp + 272 + k);
            a0.x += x0.x*w0.x + x0.y*w1.x + x0.z*w2.x + x0.w*w3.x;
            a0.y += x0.x*w0.y + x0.y*w1.y + x0.z*w2.y + x0.w*w3.y;
            a0.z += x0.x*w0.z + x0.y*w1.z + x0.z*w2.z + x0.w*w3.z;
            a0.w += x0.x*w0.w + x0.y*w1.w + x0.z*w2.w + x0.w*w3.w;
            a1.x += x1.x*w0.x + x1.y*w1.x + x1.z*w2.x + x1.w*w3.x;
            a1.y += x1.x*w0.y + x1.y*w1.y + x1.z*w2.y + x1.w*w3.y;
            a1.z += x1.x*w0.z + x1.y*w1.z + x1.z*w2.z + x1.w*w3.z;
            a1.w += x1.x*w0.w + x1.y*w1.w + x1.z*w2.w + x1.w*w3.w;
            a2.x += x2.x*w0.x + x2.y*w1.x + x2.z*w2.x + x2.w*w3.x;
            a2.y += x2.x*w0.y + x2.y*w1.y + x2.z*w2.y + x2.w*w3.y;
            a2.z += x2.x*w0.z + x2.y*w1.z + x2.z*w2.z + x2.w*w3.z;
            a2.w += x2.x*w0.w + x2.y*w1.w + x2.z*w2.w + x2.w*w3.w;
            a3.x += x3.x*w0.x + x3.y*w1.x + x3.z*w2.x + x3.w*w3.x;
            a3.y += x3.x*w0.y + x3.y*w1.y + x3.z*w2.y + x3.w*w3.y;
            a3.z += x3.x*w0.z + x3.y*w1.z + x3.z*w2.z + x3.w*w3.z;
            a3.w += x3.x*w0.w + x3.y*w1.w + x3.z*w2.w + x3.w*w3.w;
            a4.x += x4.x*w0.x + x4.y*w1.x + x4.z*w2.x + x4.w*w3.x;
            a4.y += x4.x*w0.y + x4.y*w1.y + x4.z*w2.y + x4.w*w3.y;
            a4.z += x4.x*w0.z + x4.y*w1.z + x4.z*w2.z + x4.w*w3.z;
            a4.w += x4.x*w0.w + x4.y*w1.w + x4.z*w2.w + x4.w*w3.w;
        }
        float4 acc[5] = {a0,a1,a2,a3,a4};
        #pragma unroll
        for (int i = 0; i < 5; i++){
            int r = r0 + i;
            if (r < 72){
                int n = base + r/9, m = r%9;
                float4 v = acc[i];
                if (m == 0){
                    v.x += s_b[c0]; v.y += s_b[c0+1]; v.z += s_b[c0+2]; v.w += s_b[c0+3];
                }
                *(float4*)(out + (size_t)n*576 + m*64 + c0) = v;
            }
        }
    }
}

extern "C" void kernel_launch(void* const* d_in, const int* in_sizes, int n_in,
                              void* d_out, int out_size)
{
    const float* node_input = (const float*)d_in[0];
    const float* edge_attr  = (const float*)d_in[1];
    const float* edge_scal  = (const float*)d_in[2];
    const float* W_src = (const float*)d_in[3];
    const float* b_src = (const float*)d_in[4];
    const float* W_dst = (const float*)d_in[5];
    const float* rW1   = (const float*)d_in[6];
    const float* rb1   = (const float*)d_in[7];
    const float* lng   = (const float*)d_in[8];
    const float* lnb   = (const float*)d_in[9];
    const float* rW2   = (const float*)d_in[10];
    const float* roff  = (const float*)d_in[11];
    const float* Wa    = (const float*)d_in[12];
    const float* ba    = (const float*)d_in[13];
    const float* adot  = (const float*)d_in[14];
    const float* Wv    = (const float*)d_in[15];
    const float* bv    = (const float*)d_in[16];
    const float* Wp    = (const float*)d_in[17];
    const float* bp    = (const float*)d_in[18];
    const int*   esrc  = (const int*)d_in[19];
    const int*   edst  = (const int*)d_in[20];
    float* out = (float*)d_out;

    const int smem_node = (64*128 + 40*68 + 64) * 4;
    const int smem_eA   = (64*68*2 + 64*192 + 512 + 16*68*3 + 16*192) * 4;
    const int smem_eB   = (64*128 + 144*68 + 16*192 + 192 + 128 + 128) * 4;
    const int smem_out  = (64*68 + 80*68 + 64 + 64) * 4;

    cudaFuncSetAttribute(k_node,  cudaFuncAttributeMaxDynamicSharedMemorySize, smem_node);
    cudaFuncSetAttribute(k_edgeA, cudaFuncAttributeMaxDynamicSharedMemorySize, smem_eA);
    cudaFuncSetAttribute(k_edgeB, cudaFuncAttributeMaxDynamicSharedMemorySize, smem_eB);
    cudaFuncSetAttribute(k_out,   cudaFuncAttributeMaxDynamicSharedMemorySize, smem_out);

    k_init<<<2048, 256>>>();
    k_node<<<296, 256, smem_node>>>(node_input, W_src, b_src, W_dst);
    k_edgeA<<<296, 256, smem_eA>>>(edge_scal, edge_attr, esrc, edst,
                                   rW1, rb1, lng, lnb, rW2, roff, Wa, ba, adot);
    k_edgeB<<<296, 256, smem_eB>>>(edge_attr, esrc, edst, Wv, bv);
    k_out<<<296, 256, smem_out>>>(Wp, bp, out);
}

// round 5
// speedup vs baseline: 2.0398x; 1.0443x over previous
#include <cuda_runtime.h>
#include <math.h>

#define NN 10000
#define NE 160000
#define MM 9
#define CC 64
#define HH 8

// ---------------- scratch (static device globals; no allocation) ----------------
__device__ float    g_xs[NN*MM*CC];        // node src-linear   (23 MB)
__device__ float    g_xd[NN*MM*CC];        // node dst-linear   (23 MB)
__device__ float    g_wlc[(size_t)NE*192]; // radial weights    (123 MB)
__device__ float    g_logit[NE*HH];
__device__ unsigned g_nmax[NN*HH];         // monotone-mapped float max
__device__ float    g_denom[NN*HH];
__device__ float    g_acc[NN*MM*CC];

__device__ __forceinline__ unsigned fkey(float f){
    int i = __float_as_int(f);
    return (i >= 0) ? ((unsigned)i ^ 0x80000000u) : ~(unsigned)i;
}
__device__ __forceinline__ float fdec(unsigned u){
    int i = (u & 0x80000000u) ? (int)(u ^ 0x80000000u) : (int)(~u);
    return __int_as_float(i);
}
__device__ __forceinline__ float sigf(float x){ return 1.f/(1.f + __expf(-x)); }

// packed fp32x2 FMA: d = a*b + d (elementwise on the 2-wide pack)
__device__ __forceinline__ void ffma2(unsigned long long& d,
                                      unsigned long long a,
                                      unsigned long long b){
    asm("fma.rn.f32x2 %0, %1, %2, %0;" : "+l"(d) : "l"(a), "l"(b));
}
__device__ __forceinline__ float2 up2(unsigned long long v){
    float2 r; asm("mov.b64 {%0,%1}, %2;" : "=f"(r.x), "=f"(r.y) : "l"(v)); return r;
}

__global__ void k_init(){
    int i = blockIdx.x*blockDim.x + threadIdx.x;
    int st = gridDim.x*blockDim.x;
    for (int t = i; t < NN*MM*CC; t += st) g_acc[t] = 0.f;
    for (int t = i; t < NN*HH;    t += st){ g_denom[t] = 0.f; g_nmax[t] = fkey(-INFINITY); }
}

// ================= K1: node linear (GEMM: 4 nodes -> X[40x64] @ W[64x128]) =====
__global__ __launch_bounds__(256) void k_node(
    const float* __restrict__ xin, const float* __restrict__ Ws,
    const float* __restrict__ bs,  const float* __restrict__ Wd)
{
    extern __shared__ float sm[];
    float* s_W = sm;               // [64][128]  col 0-63: Ws, 64-127: Wd
    float* s_X = s_W + 64*128;     // [40][68]
    float* s_b = s_X + 40*68;      // 64
    int tid = threadIdx.x;
    for (int t = tid; t < 8192; t += 256){
        int k = t>>7, c = t&127;
        s_W[t] = (c < 64) ? Ws[k*64 + c] : Wd[k*64 + (c-64)];
    }
    if (tid < 64) s_b[tid] = bs[tid];
    for (int t = tid; t < 4*68; t += 256) s_X[36*68 + t] = 0.f;
    __syncthreads();

    int rg = tid>>5;              // 0..7  -> rows rg*5..rg*5+4
    int c0 = (tid&31)*4;          // 0..124
    int r0 = rg*5;

    for (int base = blockIdx.x*4; base < NN; base += gridDim.x*4){
        __syncthreads();
        for (int i = tid; i < 4*576; i += 256){
            int n = i/576, rem = i - n*576;
            int row = n*9 + (rem>>6), col = rem&63;
            s_X[row*68 + col] = xin[(size_t)(base+n)*576 + rem];
        }
        __syncthreads();
        float4 a0 = {0,0,0,0}, a1 = a0, a2 = a0, a3 = a0, a4 = a0;
        const float* Xp = s_X + r0*68;
        #pragma unroll 4
        for (int k = 0; k < 64; k += 4){
            float4 w0 = *(const float4*)(s_W + (k  )*128 + c0);
            float4 w1 = *(const float4*)(s_W + (k+1)*128 + c0);
            float4 w2 = *(const float4*)(s_W + (k+2)*128 + c0);
            float4 w3 = *(const float4*)(s_W + (k+3)*128 + c0);
            float4 x0 = *(const float4*)(Xp + k);
            float4 x1 = *(const float4*)(Xp + 68 + k);
            float4 x2 = *(const float4*)(Xp + 136 + k);
            float4 x3 = *(const float4*)(Xp + 204 + k);
            float4 x4 = *(const float4*)(Xp + 272 + k);
            a0.x += x0.x*w0.x + x0.y*w1.x + x0.z*w2.x + x0.w*w3.x;
            a0.y += x0.x*w0.y + x0.y*w1.y + x0.z*w2.y + x0.w*w3.y;
            a0.z += x0.x*w0.z + x0.y*w1.z + x0.z*w2.z + x0.w*w3.z;
            a0.w += x0.x*w0.w + x0.y*w1.w + x0.z*w2.w + x0.w*w3.w;
            a1.x += x1.x*w0.x + x1.y*w1.x + x1.z*w2.x + x1.w*w3.x;
            a1.y += x1.x*w0.y + x1.y*w1.y + x1.z*w2.y + x1.w*w3.y;
            a1.z += x1.x*w0.z + x1.y*w1.z + x1.z*w2.z + x1.w*w3.z;
            a1.w += x1.x*w0.w + x1.y*w1.w + x1.z*w2.w + x1.w*w3.w;
            a2.x += x2.x*w0.x + x2.y*w1.x + x2.z*w2.x + x2.w*w3.x;
            a2.y += x2.x*w0.y + x2.y*w1.y + x2.z*w2.y + x2.w*w3.y;
            a2.z += x2.x*w0.z + x2.y*w1.z + x2.z*w2.z + x2.w*w3.z;
            a2.w += x2.x*w0.w + x2.y*w1.w + x2.z*w2.w + x2.w*w3.w;
            a3.x += x3.x*w0.x + x3.y*w1.x + x3.z*w2.x + x3.w*w3.x;
            a3.y += x3.x*w0.y + x3.y*w1.y + x3.z*w2.y + x3.w*w3.y;
            a3.z += x3.x*w0.z + x3.y*w1.z + x3.z*w2.z + x3.w*w3.z;
            a3.w += x3.x*w0.w + x3.y*w1.w + x3.z*w2.w + x3.w*w3.w;
            a4.x += x4.x*w0.x + x4.y*w1.x + x4.z*w2.x + x4.w*w3.x;
            a4.y += x4.x*w0.y + x4.y*w1.y + x4.z*w2.y + x4.w*w3.y;
            a4.z += x4.x*w0.z + x4.y*w1.z + x4.z*w2.z + x4.w*w3.z;
            a4.w += x4.x*w0.w + x4.y*w1.w + x4.z*w2.w + x4.w*w3.w;
        }
        float4 acc[5] = {a0,a1,a2,a3,a4};
        #pragma unroll
        for (int i = 0; i < 5; i++){
            int r = r0 + i;
            if (r < 36){
                int n = base + r/9, m = r%9;
                float4 v = acc[i];
                if (m == 0 && c0 < 64){
                    v.x += s_b[c0]; v.y += s_b[c0+1]; v.z += s_b[c0+2]; v.w += s_b[c0+3];
                }
                if (c0 < 64) *(float4*)(g_xs + (size_t)n*576 + m*64 + c0) = v;
                else         *(float4*)(g_xd + (size_t)n*576 + m*64 + (c0-64)) = v;
            }
        }
    }
}

// ================= K2: radial MLP + alpha logits (16 edges/iter) ================
__global__ __launch_bounds__(256) void k_edgeA(
    const float* __restrict__ esc, const float* __restrict__ eattr,
    const int* __restrict__ esrc,  const int* __restrict__ edst,
    const float* __restrict__ W1,  const float* __restrict__ b1,
    const float* __restrict__ lng, const float* __restrict__ lnb,
    const float* __restrict__ W2,  const float* __restrict__ off,
    const float* __restrict__ Wa,  const float* __restrict__ ba,
    const float* __restrict__ adot)
{
    extern __shared__ float sm[];
    float* s_W1 = sm;               // [64][68]
    float* s_Wa = s_W1 + 64*68;     // [64][68]
    float* s_W2 = s_Wa + 64*68;     // [64][192] raw
    float* cb   = s_W2 + 64*192;    // b1|lng|lnb|ba|adot|off  = 512
    float* s_S  = cb + 512;         // [16][68]
    float* s_H  = s_S + 16*68;      // [16][68]
    float* s_M0 = s_H + 16*68;      // [16][68]
    float* s_WL = s_M0 + 16*68;     // [16][192]
    int tid = threadIdx.x;
    for (int t = tid; t < 4096; t += 256){
        int k = t>>6, j = t&63;
        s_W1[k*68+j] = W1[t]; s_Wa[k*68+j] = Wa[t];
    }
    for (int t = tid; t < 12288; t += 256) s_W2[t] = W2[t];
    if (tid < 64){
        cb[tid] = b1[tid]; cb[64+tid] = lng[tid]; cb[128+tid] = lnb[tid];
        cb[192+tid] = ba[tid]; cb[256+tid] = adot[tid];
    }
    for (int t = tid; t < 192; t += 256) cb[320+t] = off[t];
    __syncthreads();

    int rg = tid>>4;            // 0..15 (edge row)
    int tx = tid&15;
    int c0 = tx*4;

    for (int base = blockIdx.x*16; base < NE; base += gridDim.x*16){
        __syncthreads();
        for (int i = tid; i < 16*64; i += 256){
            int e = i>>6, c = i&63;
            s_S[e*68 + c] = esc[(size_t)(base+e)*64 + c];
        }
        __syncthreads();
        // GEMM1: H = S @ W1   (k vectorized by 4)
        {
            float4 a = {0,0,0,0};
            const float* Xp = s_S + rg*68;
            #pragma unroll 4
            for (int k = 0; k < 64; k += 4){
                float4 x = *(const float4*)(Xp + k);
                float4 w0 = *(const float4*)(s_W1 + (k  )*68 + c0);
                float4 w1 = *(const float4*)(s_W1 + (k+1)*68 + c0);
                float4 w2 = *(const float4*)(s_W1 + (k+2)*68 + c0);
                float4 w3 = *(const float4*)(s_W1 + (k+3)*68 + c0);
                a.x += x.x*w0.x + x.y*w1.x + x.z*w2.x + x.w*w3.x;
                a.y += x.x*w0.y + x.y*w1.y + x.z*w2.y + x.w*w3.y;
                a.z += x.x*w0.z + x.y*w1.z + x.z*w2.z + x.w*w3.z;
                a.w += x.x*w0.w + x.y*w1.w + x.z*w2.w + x.w*w3.w;
            }
            a.x += cb[c0]; a.y += cb[c0+1]; a.z += cb[c0+2]; a.w += cb[c0+3];
            float s = a.x+a.y+a.z+a.w;
            float q = a.x*a.x+a.y*a.y+a.z*a.z+a.w*a.w;
            #pragma unroll
            for (int o = 8; o > 0; o >>= 1){
                s += __shfl_xor_sync(0xffffffffu, s, o);
                q += __shfl_xor_sync(0xffffffffu, q, o);
            }
            float mu = s*(1.f/64.f);
            float var = q*(1.f/64.f) - mu*mu;
            float rs = rsqrtf(var + 1e-5f);
            float4 h;
            h.x = (a.x-mu)*rs*cb[64+c0  ] + cb[128+c0  ];
            h.y = (a.y-mu)*rs*cb[64+c0+1] + cb[128+c0+1];
            h.z = (a.z-mu)*rs*cb[64+c0+2] + cb[128+c0+2];
            h.w = (a.w-mu)*rs*cb[64+c0+3] + cb[128+c0+3];
            h.x *= sigf(h.x); h.y *= sigf(h.y); h.z *= sigf(h.z); h.w *= sigf(h.w);
            *(float4*)(s_H + rg*68 + c0) = h;
        }
        __syncthreads();
        // GEMM2: WL = H @ W2   (k vectorized by 4 on x)
        {
            int rgr = tid>>6;
            int cc  = tid&63;
            float acc[4][3] = {{0,0,0},{0,0,0},{0,0,0},{0,0,0}};
            #pragma unroll 2
            for (int k = 0; k < 64; k += 4){
                float4 x0 = *(const float4*)(s_H + (rgr   )*68 + k);
                float4 x1 = *(const float4*)(s_H + (rgr+4 )*68 + k);
                float4 x2 = *(const float4*)(s_H + (rgr+8 )*68 + k);
                float4 x3 = *(const float4*)(s_H + (rgr+12)*68 + k);
                {
                    float w0 = s_W2[(k  )*192 + cc], w1 = s_W2[(k  )*192 + cc + 64], w2 = s_W2[(k  )*192 + cc + 128];
                    acc[0][0]+=x0.x*w0; acc[0][1]+=x0.x*w1; acc[0][2]+=x0.x*w2;
                    acc[1][0]+=x1.x*w0; acc[1][1]+=x1.x*w1; acc[1][2]+=x1.x*w2;
                    acc[2][0]+=x2.x*w0; acc[2][1]+=x2.x*w1; acc[2][2]+=x2.x*w2;
                    acc[3][0]+=x3.x*w0; acc[3][1]+=x3.x*w1; acc[3][2]+=x3.x*w2;
                }
                {
                    float w0 = s_W2[(k+1)*192 + cc], w1 = s_W2[(k+1)*192 + cc + 64], w2 = s_W2[(k+1)*192 + cc + 128];
                    acc[0][0]+=x0.y*w0; acc[0][1]+=x0.y*w1; acc[0][2]+=x0.y*w2;
                    acc[1][0]+=x1.y*w0; acc[1][1]+=x1.y*w1; acc[1][2]+=x1.y*w2;
                    acc[2][0]+=x2.y*w0; acc[2][1]+=x2.y*w1; acc[2][2]+=x2.y*w2;
                    acc[3][0]+=x3.y*w0; acc[3][1]+=x3.y*w1; acc[3][2]+=x3.y*w2;
                }
                {
                    float w0 = s_W2[(k+2)*192 + cc], w1 = s_W2[(k+2)*192 + cc + 64], w2 = s_W2[(k+2)*192 + cc + 128];
                    acc[0][0]+=x0.z*w0; acc[0][1]+=x0.z*w1; acc[0][2]+=x0.z*w2;
                    acc[1][0]+=x1.z*w0; acc[1][1]+=x1.z*w1; acc[1][2]+=x1.z*w2;
                    acc[2][0]+=x2.z*w0; acc[2][1]+=x2.z*w1; acc[2][2]+=x2.z*w2;
                    acc[3][0]+=x3.z*w0; acc[3][1]+=x3.z*w1; acc[3][2]+=x3.z*w2;
                }
                {
                    float w0 = s_W2[(k+3)*192 + cc], w1 = s_W2[(k+3)*192 + cc + 64], w2 = s_W2[(k+3)*192 + cc + 128];
                    acc[0][0]+=x0.w*w0; acc[0][1]+=x0.w*w1; acc[0][2]+=x0.w*w2;
                    acc[1][0]+=x1.w*w0; acc[1][1]+=x1.w*w1; acc[1][2]+=x1.w*w2;
                    acc[2][0]+=x2.w*w0; acc[2][1]+=x2.w*w1; acc[2][2]+=x2.w*w2;
                    acc[3][0]+=x3.w*w0; acc[3][1]+=x3.w*w1; acc[3][2]+=x3.w*w2;
                }
            }
            #pragma unroll
            for (int i = 0; i < 4; i++){
                int r = rgr + i*4;
                #pragma unroll
                for (int j = 0; j < 3; j++){
                    float v = acc[i][j] + cb[320 + cc + 64*j];
                    s_WL[r*192 + cc + 64*j] = v;
                    g_wlc[(size_t)(base+r)*192 + cc + 64*j] = v;
                }
            }
        }
        __syncthreads();
        // M0 build
        int dst;
        {
            int e = rg;
            int src = esrc[base+e]; dst = edst[base+e];
            float ea0 = eattr[(size_t)(base+e)*9];
            float4 xs = *(const float4*)(g_xs + (size_t)src*576 + c0);
            float4 xd = *(const float4*)(g_xd + (size_t)dst*576 + c0);
            float4 wl = *(const float4*)(s_WL + e*192 + c0);
            float4 m0;
            m0.x = (xs.x+xd.x)*ea0*wl.x; m0.y = (xs.y+xd.y)*ea0*wl.y;
            m0.z = (xs.z+xd.z)*ea0*wl.z; m0.w = (xs.w+xd.w)*ea0*wl.w;
            *(float4*)(s_M0 + e*68 + c0) = m0;
        }
        __syncthreads();
        // GEMM3: alpha logits   (k vectorized by 4)
        {
            float4 a = {0,0,0,0};
            const float* Xp = s_M0 + rg*68;
            #pragma unroll 4
            for (int k = 0; k < 64; k += 4){
                float4 x = *(const float4*)(Xp + k);
                float4 w0 = *(const float4*)(s_Wa + (k  )*68 + c0);
                float4 w1 = *(const float4*)(s_Wa + (k+1)*68 + c0);
                float4 w2 = *(const float4*)(s_Wa + (k+2)*68 + c0);
                float4 w3 = *(const float4*)(s_Wa + (k+3)*68 + c0);
                a.x += x.x*w0.x + x.y*w1.x + x.z*w2.x + x.w*w3.x;
                a.y += x.x*w0.y + x.y*w1.y + x.z*w2.y + x.w*w3.y;
                a.z += x.x*w0.z + x.y*w1.z + x.z*w2.z + x.w*w3.z;
                a.w += x.x*w0.w + x.y*w1.w + x.z*w2.w + x.w*w3.w;
            }
            a.x += cb[192+c0]; a.y += cb[192+c0+1]; a.z += cb[192+c0+2]; a.w += cb[192+c0+3];
            a.x = 0.2f*a.x + 0.8f*a.x*sigf(a.x);
            a.y = 0.2f*a.y + 0.8f*a.y*sigf(a.y);
            a.z = 0.2f*a.z + 0.8f*a.z*sigf(a.z);
            a.w = 0.2f*a.w + 0.8f*a.w*sigf(a.w);
            float s4 = a.x*cb[256+c0] + a.y*cb[256+c0+1] + a.z*cb[256+c0+2] + a.w*cb[256+c0+3];
            float lg = s4 + __shfl_xor_sync(0xffffffffu, s4, 1);
            if ((tx & 1) == 0){
                int h = tx >> 1;
                g_logit[(size_t)(base+rg)*8 + h] = lg;
                atomicMax(&g_nmax[dst*8 + h], fkey(lg));
            }
        }
    }
}

// ================= K3: value GEMM + weighted scatter, FFMA2, warp-per-edge ======
// Lane l owns value cols {l, l+32} and gate cols {64+l, 96+l}; Wv stored
// transposed [col][k] so k-pairs pack into f32x2 operands with zero moves.
// All smem slots are per-warp private: no __syncthreads in the loop.
__global__ __launch_bounds__(256, 2) void k_edgeB(
    const float* __restrict__ eattr, const int* __restrict__ esrc,
    const int* __restrict__ edst,    const float* __restrict__ Wv,
    const float* __restrict__ bv)
{
    extern __shared__ float sm[];
    float* s_Wt = sm;                 // [128][68] transposed: s_Wt[c*68+k] = Wv[k*128+c]
    float* s_X  = s_Wt + 128*68;      // [8 warps][9 rows][68]
    float* s_wl = s_X + 8*9*68;       // [8][192]
    float* s_ea = s_wl + 8*192;       // [8][12]
    float* s_sw = s_ea + 96;          // [8][8]
    float* s_bv = s_sw + 64;          // 128
    int tid = threadIdx.x;
    for (int t = tid; t < 8192; t += 256){
        int k = t>>7, c = t&127;
        s_Wt[c*68 + k] = Wv[t];
    }
    if (tid < 128) s_bv[tid] = bv[tid];
    __syncthreads();

    int w = tid>>5, lane = tid&31;
    float* myX  = s_X  + w*9*68;
    float* mywl = s_wl + w*192;
    float* myea = s_ea + w*12;
    float* mysw = s_sw + w*8;
    const float* Wc0 = s_Wt + lane*68;
    const float* Wc1 = s_Wt + (lane+32)*68;
    const float* Gc0 = s_Wt + (64+lane)*68;
    const float* Gc1 = s_Wt + (96+lane)*68;
    int gw = blockIdx.x*8 + w;

    for (int e = gw; e < NE; e += 2368){
        int src = esrc[e], dst = edst[e];
        // ---- metadata (per-warp) ----
        #pragma unroll
        for (int t = lane; t < 48; t += 32){
            float4 v = *(const float4*)(g_wlc + (size_t)e*192 + t*4);
            *(float4*)(mywl + t*4) = v;
        }
        if (lane < 9) myea[lane] = eattr[(size_t)e*9 + lane];
        if (lane < 8){
            float lg = g_logit[(size_t)e*8 + lane];
            float mx = fdec(g_nmax[dst*8 + lane]);
            float ww = __expf(lg - mx);
            mysw[lane] = ww;
            atomicAdd(&g_denom[dst*8 + lane], ww);
        }
        __syncwarp();
        // ---- build X: msg rows ----
        #pragma unroll
        for (int m = 0; m < 9; m++){
            int lsel = (m==0) ? 0 : (m<4) ? 1 : 2;
            float2 a = *(const float2*)(g_xs + (size_t)src*576 + m*64 + 2*lane);
            float2 b = *(const float2*)(g_xd + (size_t)dst*576 + m*64 + 2*lane);
            float eam = myea[m];
            float2 wl2 = *(const float2*)(mywl + lsel*64 + 2*lane);
            float2 v; v.x = (a.x+b.x)*eam*wl2.x; v.y = (a.y+b.y)*eam*wl2.y;
            *(float2*)(myX + m*68 + 2*lane) = v;
        }
        __syncwarp();
        // ---- FFMA2 GEMM: acc pairs hold even/odd-k partials ----
        unsigned long long accv[9][2];
        unsigned long long accg[2];
        #pragma unroll
        for (int m = 0; m < 9; m++){ accv[m][0] = 0ull; accv[m][1] = 0ull; }
        accg[0] = 0ull; accg[1] = 0ull;
        #pragma unroll 4
        for (int k = 0; k < 64; k += 4){
            ulonglong2 w0 = *(const ulonglong2*)(Wc0 + k);
            ulonglong2 w1 = *(const ulonglong2*)(Wc1 + k);
            ulonglong2 q0 = *(const ulonglong2*)(Gc0 + k);
            ulonglong2 q1 = *(const ulonglong2*)(Gc1 + k);
            {
                ulonglong2 x = *(const ulonglong2*)(myX + k);
                ffma2(accv[0][0], x.x, w0.x); ffma2(accv[0][0], x.y, w0.y);
                ffma2(accv[0][1], x.x, w1.x); ffma2(accv[0][1], x.y, w1.y);
                ffma2(accg[0],    x.x, q0.x); ffma2(accg[0],    x.y, q0.y);
                ffma2(accg[1],    x.x, q1.x); ffma2(accg[1],    x.y, q1.y);
            }
            #pragma unroll
            for (int m = 1; m < 9; m++){
                ulonglong2 x = *(const ulonglong2*)(myX + m*68 + k);
                ffma2(accv[m][0], x.x, w0.x); ffma2(accv[m][0], x.y, w0.y);
                ffma2(accv[m][1], x.x, w1.x); ffma2(accv[m][1], x.y, w1.y);
            }
        }
        __syncwarp();   // all GEMM reads of myX done before overwrite
        // ---- epilogue: reduce pairs, postprocess, stage into myX ----
        {
            float2 gp0 = up2(accg[0]);
            float2 gp1 = up2(accg[1]);
            float gate0 = sigf(gp0.x + gp0.y + s_bv[64+lane]);
            float gate1 = sigf(gp1.x + gp1.y + s_bv[96+lane]);
            float whA = mysw[lane>>3];
            float whB = mysw[(lane+32)>>3];
            #pragma unroll
            for (int m = 0; m < 9; m++){
                int lsel = (m==0) ? 0 : (m<4) ? 1 : 2;
                float2 vA = up2(accv[m][0]);
                float2 vB = up2(accv[m][1]);
                float yA = vA.x + vA.y;
                float yB = vB.x + vB.y;
                float oA, oB;
                if (m == 0){
                    yA += s_bv[lane]; yB += s_bv[lane+32];
                    oA = yA * sigf(yA); oB = yB * sigf(yB);
                } else {
                    oA = yA * gate0; oB = yB * gate1;
                }
                float eam = myea[m];
                oA *= eam * mywl[lsel*64 + lane]      * whA;
                oB *= eam * mywl[lsel*64 + lane + 32] * whB;
                myX[m*68 + lane]      = oA;
                myX[m*68 + lane + 32] = oB;
            }
        }
        __syncwarp();
        // ---- float4 atomic scatter ----
        float* accp = g_acc + (size_t)dst*576;
        #pragma unroll
        for (int t = lane; t < 144; t += 32){
            int r = t>>4, c4 = (t&15)*4;
            float4 v = *(const float4*)(myX + r*68 + c4);
            atomicAdd((float4*)(accp + r*64 + c4), v);
        }
        __syncwarp();
    }
}

// ================= K4: normalize + projection (8 nodes/iter) ====================
__global__ __launch_bounds__(256) void k_out(
    const float* __restrict__ Wp, const float* __restrict__ bp, float* __restrict__ out)
{
    extern __shared__ float sm[];
    float* s_W  = sm;              // [64][68]
    float* s_X  = s_W + 64*68;     // [80][68]
    float* s_b  = s_X + 80*68;     // 64
    float* s_inv= s_b + 64;        // 64
    int tid = threadIdx.x;
    for (int t = tid; t < 4096; t += 256){
        int k = t>>6, j = t&63;
        s_W[k*68 + j] = Wp[t];
    }
    if (tid < 64) s_b[tid] = bp[tid];
    for (int t = tid; t < 8*68; t += 256) s_X[72*68 + t] = 0.f;
    __syncthreads();

    int rg = tid>>4, tx = tid&15, c0 = tx*4, r0 = rg*5;

    for (int base = blockIdx.x*8; base < NN; base += gridDim.x*8){
        __syncthreads();
        if (tid < 64){
            int e = tid>>3, h = tid&7;
            s_inv[tid] = 1.f/(g_denom[(base+e)*8 + h] + 1e-16f);
        }
        __syncthreads();
        for (int i = tid; i < 8*576; i += 256){
            int n = i/576, rem = i - n*576;
            int row = n*9 + (rem>>6), col = rem&63;
            s_X[row*68 + col] = g_acc[(size_t)(base+n)*576 + rem] * s_inv[n*8 + (col>>3)];
        }
        __syncthreads();
        float4 a0 = {0,0,0,0}, a1 = a0, a2 = a0, a3 = a0, a4 = a0;
        const float* Xp = s_X + r0*68;
        #pragma unroll 4
        for (int k = 0; k < 64; k += 4){
            float4 w0 = *(const float4*)(s_W + (k  )*68 + c0);
            float4 w1 = *(const float4*)(s_W + (k+1)*68 + c0);
            float4 w2 = *(const float4*)(s_W + (k+2)*68 + c0);
            float4 w3 = *(const float4*)(s_W + (k+3)*68 + c0);
            float4 x0 = *(const float4*)(Xp + k);
            float4 x1 = *(const float4*)(Xp + 68 + k);
            float4 x2 = *(const float4*)(Xp + 136 + k);
            float4 x3 = *(const float4*)(Xp + 204 + k);
            float4 x4 = *(const float4*)(Xp + 272 + k);
            a0.x += x0.x*w0.x + x0.y*w1.x + x0.z*w2.x + x0.w*w3.x;
            a0.y += x0.x*w0.y + x0.y*w1.y + x0.z*w2.y + x0.w*w3.y;
            a0.z += x0.x*w0.z + x0.y*w1.z + x0.z*w2.z + x0.w*w3.z;
            a0.w += x0.x*w0.w + x0.y*w1.w + x0.z*w2.w + x0.w*w3.w;
            a1.x += x1.x*w0.x + x1.y*w1.x + x1.z*w2.x + x1.w*w3.x;
            a1.y += x1.x*w0.y + x1.y*w1.y + x1.z*w2.y + x1.w*w3.y;
            a1.z += x1.x*w0.z + x1.y*w1.z + x1.z*w2.z + x1.w*w3.z;
            a1.w += x1.x*w0.w + x1.y*w1.w + x1.z*w2.w + x1.w*w3.w;
            a2.x += x2.x*w0.x + x2.y*w1.x + x2.z*w2.x + x2.w*w3.x;
            a2.y += x2.x*w0.y + x2.y*w1.y + x2.z*w2.y + x2.w*w3.y;
            a2.z += x2.x*w0.z + x2.y*w1.z + x2.z*w2.z + x2.w*w3.z;
            a2.w += x2.x*w0.w + x2.y*w1.w + x2.z*w2.w + x2.w*w3.w;
            a3.x += x3.x*w0.x + x3.y*w1.x + x3.z*w2.x + x3.w*w3.x;
            a3.y += x3.x*w0.y + x3.y*w1.y + x3.z*w2.y + x3.w*w3.y;
            a3.z += x3.x*w0.z + x3.y*w1.z + x3.z*w2.z + x3.w*w3.z;
            a3.w += x3.x*w0.w + x3.y*w1.w + x3.z*w2.w + x3.w*w3.w;
            a4.x += x4.x*w0.x + x4.y*w1.x + x4.z*w2.x + x4.w*w3.x;
            a4.y += x4.x*w0.y + x4.y*w1.y + x4.z*w2.y + x4.w*w3.y;
            a4.z += x4.x*w0.z + x4.y*w1.z + x4.z*w2.z + x4.w*w3.z;
            a4.w += x4.x*w0.w + x4.y*w1.w + x4.z*w2.w + x4.w*w3.w;
        }
        float4 acc[5] = {a0,a1,a2,a3,a4};
        #pragma unroll
        for (int i = 0; i < 5; i++){
            int r = r0 + i;
            if (r < 72){
                int n = base + r/9, m = r%9;
                float4 v = acc[i];
                if (m == 0){
                    v.x += s_b[c0]; v.y += s_b[c0+1]; v.z += s_b[c0+2]; v.w += s_b[c0+3];
                }
                *(float4*)(out + (size_t)n*576 + m*64 + c0) = v;
            }
        }
    }
}

extern "C" void kernel_launch(void* const* d_in, const int* in_sizes, int n_in,
                              void* d_out, int out_size)
{
    const float* node_input = (const float*)d_in[0];
    const float* edge_attr  = (const float*)d_in[1];
    const float* edge_scal  = (const float*)d_in[2];
    const float* W_src = (const float*)d_in[3];
    const float* b_src = (const float*)d_in[4];
    const float* W_dst = (const float*)d_in[5];
    const float* rW1   = (const float*)d_in[6];
    const float* rb1   = (const float*)d_in[7];
    const float* lng   = (const float*)d_in[8];
    const float* lnb   = (const float*)d_in[9];
    const float* rW2   = (const float*)d_in[10];
    const float* roff  = (const float*)d_in[11];
    const float* Wa    = (const float*)d_in[12];
    const float* ba    = (const float*)d_in[13];
    const float* adot  = (const float*)d_in[14];
    const float* Wv    = (const float*)d_in[15];
    const float* bv    = (const float*)d_in[16];
    const float* Wp    = (const float*)d_in[17];
    const float* bp    = (const float*)d_in[18];
    const int*   esrc  = (const int*)d_in[19];
    const int*   edst  = (const int*)d_in[20];
    float* out = (float*)d_out;

    const int smem_node = (64*128 + 40*68 + 64) * 4;
    const int smem_eA   = (64*68*2 + 64*192 + 512 + 16*68*3 + 16*192) * 4;
    const int smem_eB   = (128*68 + 8*9*68 + 8*192 + 96 + 64 + 128) * 4;
    const int smem_out  = (64*68 + 80*68 + 64 + 64) * 4;

    cudaFuncSetAttribute(k_node,  cudaFuncAttributeMaxDynamicSharedMemorySize, smem_node);
    cudaFuncSetAttribute(k_edgeA, cudaFuncAttributeMaxDynamicSharedMemorySize, smem_eA);
    cudaFuncSetAttribute(k_edgeB, cudaFuncAttributeMaxDynamicSharedMemorySize, smem_eB);
    cudaFuncSetAttribute(k_out,   cudaFuncAttributeMaxDynamicSharedMemorySize, smem_out);

    k_init<<<2048, 256>>>();
    k_node<<<296, 256, smem_node>>>(node_input, W_src, b_src, W_dst);
    k_edgeA<<<296, 256, smem_eA>>>(edge_scal, edge_attr, esrc, edst,
                                   rW1, rb1, lng, lnb, rW2, roff, Wa, ba, adot);
    k_edgeB<<<296, 256, smem_eB>>>(edge_attr, esrc, edst, Wv, bv);
    k_out<<<296, 256, smem_out>>>(Wp, bp, out);
}